// round 13
// baseline (speedup 1.0000x reference)
#include <cuda_runtime.h>
#include <cuda_bf16.h>
#include <cstdint>
#include <math.h>

#define D_MODEL 1024
#define D_STATE 16
#define DT_RANK 64
#define NBATCH 2
#define SEQ 2048
#define NROWS (NBATCH*SEQ)   // 4096
#define NPROJ 96
#define NC 64                // chunks per sequence
#define CT 32                // chunk length
#define NTOT 1152            // 1024 (w_in) + 96 (P) + 32 pad

// ---------------- scratch (device globals) ---------------------------------
__device__ float g_xin [NROWS * D_MODEL];
__device__ float g_proj[NROWS * NPROJ];              // dt_low | B | C
__device__ float g_dt  [NROWS * D_MODEL];
__device__ float g_A   [D_MODEL * D_STATE];          // -exp(A_log)
__device__ float g_A2  [D_MODEL * D_STATE];          // -exp(A_log) * log2(e)
__device__ float g_inp [NROWS * D_STATE];
__device__ float g_S   [NBATCH * NC * D_MODEL];
__device__ float g_L   [NBATCH * NC * D_MODEL * D_STATE];
__device__ float g_hs  [NBATCH * NC * D_MODEL * D_STATE];
// GEMM operands
__device__ __nv_bfloat16 g_xh [NROWS * D_MODEL];
__device__ __nv_bfloat16 g_xl [NROWS * D_MODEL];
__device__ __nv_bfloat16 g_wth[NTOT * D_MODEL];      // [w_in | P]^T hi  [n][k]
__device__ __nv_bfloat16 g_wtl[NTOT * D_MODEL];      // [w_in | P]^T lo  [n][k]
__device__ float g_P   [D_MODEL * NPROJ];            // w_in @ w_x

#define LOG2E 1.4426950408889634f

// ---------------- PTX helpers (family-portable) -----------------------------
__device__ __forceinline__ uint32_t smem_u32(const void* p) {
    uint32_t a;
    asm("{ .reg .u64 t; cvta.to.shared.u64 t, %1; cvt.u32.u64 %0, t; }"
        : "=r"(a) : "l"(p));
    return a;
}
__device__ __forceinline__ float ex2(float x) {
    float r;
    asm("ex2.approx.ftz.f32 %0, %1;" : "=f"(r) : "f"(x));
    return r;
}
__device__ __forceinline__ void cp16(uint32_t dst, const void* src) {
    asm volatile("cp.async.cg.shared.global [%0], [%1], 16;"
                 :: "r"(dst), "l"(src) : "memory");
}
#define CP_COMMIT() asm volatile("cp.async.commit_group;" ::: "memory")
#define CP_WAIT1()  asm volatile("cp.async.wait_group 1;" ::: "memory")
#define CP_WAIT0()  asm volatile("cp.async.wait_group 0;" ::: "memory")

#define LDSM4(r0,r1,r2,r3,addr) \
    asm volatile("ldmatrix.sync.aligned.m8n8.x4.shared.b16 {%0,%1,%2,%3}, [%4];" \
        : "=r"(r0),"=r"(r1),"=r"(r2),"=r"(r3) : "r"(addr))
#define LDSM2(r0,r1,addr) \
    asm volatile("ldmatrix.sync.aligned.m8n8.x2.shared.b16 {%0,%1}, [%2];" \
        : "=r"(r0),"=r"(r1) : "r"(addr))

#define MMA16816(d, a, b) \
    asm volatile("mma.sync.aligned.m16n8k16.row.col.f32.bf16.bf16.f32 " \
        "{%0,%1,%2,%3}, {%4,%5,%6,%7}, {%8,%9}, {%0,%1,%2,%3};" \
        : "+f"((d)[0]),"+f"((d)[1]),"+f"((d)[2]),"+f"((d)[3]) \
        : "r"((a)[0]),"r"((a)[1]),"r"((a)[2]),"r"((a)[3]), \
          "r"((b)[0]),"r"((b)[1]))

// ---------------- K_conv: split x into bf16 hi/lo (2-wide); A / A2 prep -----
__global__ __launch_bounds__(256) void k_conv_x(const float* __restrict__ x,
                                                const float* __restrict__ A_log) {
    int i = blockIdx.x * 256 + threadIdx.x;
    {
        float2 f = *(const float2*)(x + i * 2);
        __nv_bfloat16 h0 = __float2bfloat16(f.x);
        __nv_bfloat16 h1 = __float2bfloat16(f.y);
        __nv_bfloat162 hv; hv.x = h0; hv.y = h1;
        *(__nv_bfloat162*)(g_xh + i * 2) = hv;
        __nv_bfloat162 lv;
        lv.x = __float2bfloat16(f.x - __bfloat162float(h0));
        lv.y = __float2bfloat16(f.y - __bfloat162float(h1));
        *(__nv_bfloat162*)(g_xl + i * 2) = lv;
    }
    if (i < D_MODEL * D_STATE / 2) {
        float2 al = *(const float2*)(A_log + i * 2);
        float a0 = -__expf(al.x), a1 = -__expf(al.y);
        *(float2*)(g_A  + i * 2) = make_float2(a0, a1);
        *(float2*)(g_A2 + i * 2) = make_float2(a0 * LOG2E, a1 * LOG2E);
    }
}

// ---------------- K_prep1: P = w_in(1024x1024) @ w_x(1024x96) ---------------
__global__ __launch_bounds__(256) void k_prep1(const float* __restrict__ Win,
                                               const float* __restrict__ Wx) {
    __shared__ float As[32][16];
    __shared__ float Bs[32][96];
    int tid = threadIdx.x;
    int row0 = blockIdx.x * 16;
    int tm = tid >> 4, tn = tid & 15;
    float acc[6];
    #pragma unroll
    for (int j = 0; j < 6; j++) acc[j] = 0.f;

    for (int k0 = 0; k0 < D_MODEL; k0 += 32) {
        #pragma unroll
        for (int q = 0; q < 2; q++) {
            int idx = tid + q * 256;
            int m = idx >> 5, kk = idx & 31;
            As[kk][m] = Win[(row0 + m) * D_MODEL + k0 + kk];
        }
        #pragma unroll
        for (int q = 0; q < 3; q++) {
            int f4 = tid + q * 256;
            int kk = f4 / 24, cg = f4 % 24;
            float4 v = *(const float4*)(Wx + (k0 + kk) * NPROJ + cg * 4);
            *(float4*)&Bs[kk][cg * 4] = v;
        }
        __syncthreads();
        #pragma unroll
        for (int k = 0; k < 32; k++) {
            float a = As[k][tm];
            #pragma unroll
            for (int j = 0; j < 6; j++) acc[j] += a * Bs[k][tn * 6 + j];
        }
        __syncthreads();
    }
    #pragma unroll
    for (int j = 0; j < 6; j++)
        g_P[(row0 + tm) * NPROJ + tn * 6 + j] = acc[j];
}

// ---------------- K_prep_w: transpose+split [w_in | P | 0] -> hi/lo ---------
__global__ void k_prep_w(const float* __restrict__ Win) {
    __shared__ float t[32][33];
    int nb = blockIdx.x * 32, kb = blockIdx.y * 32;
    int tx = threadIdx.x, ty = threadIdx.y;
    int tid = ty * 32 + tx;
    #pragma unroll
    for (int i = 0; i < 32; i += 8) {
        int k = kb + ty + i, n = nb + tx;
        float v;
        if (n < 1024)      v = Win[k * D_MODEL + n];
        else if (n < 1120) v = g_P[k * NPROJ + (n - 1024)];
        else               v = 0.f;
        t[ty + i][tx] = v;
    }
    __syncthreads();
    #pragma unroll
    for (int q = 0; q < 2; q++) {
        int idx = tid + q * 256;
        int nn  = idx >> 4;
        int kk2 = (idx & 15) * 2;
        float f0 = t[kk2][nn], f1 = t[kk2 + 1][nn];
        __nv_bfloat16 h0 = __float2bfloat16(f0);
        __nv_bfloat16 h1 = __float2bfloat16(f1);
        __nv_bfloat162 hv; hv.x = h0; hv.y = h1;
        __nv_bfloat162 lv;
        lv.x = __float2bfloat16(f0 - __bfloat162float(h0));
        lv.y = __float2bfloat16(f1 - __bfloat162float(h1));
        int n = nb + nn, k = kb + kk2;
        *(__nv_bfloat162*)(g_wth + n * D_MODEL + k) = hv;
        *(__nv_bfloat162*)(g_wtl + n * D_MODEL + k) = lv;
    }
}

// ---------------- K1: mma GEMM x(4096x1024) @ [w_in|P] (split-launch) -------
#define TILE_B (128 * 64)
#define STAGE_B (4 * TILE_B)
#define NSTAGE 3
#define GEMM_SMEM (NSTAGE * STAGE_B)
#define NT (D_MODEL / 32)

__device__ __forceinline__ uint32_t swz(int r, int c) {
    return (uint32_t)(r * 64 + ((c ^ ((r >> 1) & 3)) << 4));
}

__global__ __launch_bounds__(256, 2) void k_gemm_mma(int nbase) {
    extern __shared__ char smem[];
    uint32_t sb = smem_u32(smem);
    int tid = threadIdx.x, wid = tid >> 5, lane = tid & 31;
    int n0 = (blockIdx.x + nbase) * 128, m0 = blockIdx.y * 128;
    int wm = wid >> 2, wn = wid & 3;

    const __nv_bfloat16* srcs[4] = {
        g_xh  + m0 * D_MODEL, g_xl  + m0 * D_MODEL,
        g_wth + n0 * D_MODEL, g_wtl + n0 * D_MODEL };

    int r0 = tid >> 2,        c0 = tid & 3;
    int r1 = (tid >> 2) + 64, c1 = tid & 3;
    uint32_t d0 = swz(r0, c0), d1 = swz(r1, c1);

    #pragma unroll
    for (int s = 0; s < 2; s++) {
        uint32_t stb = sb + s * STAGE_B;
        int k0 = s * 32;
        #pragma unroll
        for (int tk = 0; tk < 4; tk++) {
            cp16(stb + tk * TILE_B + d0, srcs[tk] + r0 * D_MODEL + k0 + c0 * 8);
            cp16(stb + tk * TILE_B + d1, srcs[tk] + r1 * D_MODEL + k0 + c1 * 8);
        }
        CP_COMMIT();
    }

    float acc[4][4][4];
    #pragma unroll
    for (int mf = 0; mf < 4; mf++)
        #pragma unroll
        for (int nf = 0; nf < 4; nf++)
            #pragma unroll
            for (int q = 0; q < 4; q++) acc[mf][nf][q] = 0.f;

    int aRow = wm * 64 + (lane & 15);
    int aCh  = lane >> 4;
    int bRow = wn * 32 + (lane & 7);
    int bCh  = (lane >> 3) & 1;

    int stg_idx = 0;
    for (int kt = 0; kt < NT; kt++) {
        if (kt + 1 < NT) CP_WAIT1(); else CP_WAIT0();
        __syncthreads();

        if (kt + 2 < NT) {
            int k0 = (kt + 2) * 32;
            int s = stg_idx + 2; if (s >= NSTAGE) s -= NSTAGE;
            uint32_t stb = sb + s * STAGE_B;
            #pragma unroll
            for (int tk = 0; tk < 4; tk++) {
                cp16(stb + tk * TILE_B + d0, srcs[tk] + r0 * D_MODEL + k0 + c0 * 8);
                cp16(stb + tk * TILE_B + d1, srcs[tk] + r1 * D_MODEL + k0 + c1 * 8);
            }
            CP_COMMIT();
        }

        uint32_t stg = sb + stg_idx * STAGE_B;
        uint32_t Ah = stg, Al = stg + TILE_B;
        uint32_t Bh = stg + 2 * TILE_B, Bl = stg + 3 * TILE_B;

        #pragma unroll
        for (int ks = 0; ks < 2; ks++) {
            uint32_t bh[4][2], bl[4][2];
            #pragma unroll
            for (int nf = 0; nf < 4; nf++) {
                uint32_t boff = swz(bRow + nf * 8, ks * 2 + bCh);
                LDSM2(bh[nf][0], bh[nf][1], Bh + boff);
                LDSM2(bl[nf][0], bl[nf][1], Bl + boff);
            }
            #pragma unroll
            for (int mf = 0; mf < 4; mf++) {
                uint32_t aoff = swz(aRow + mf * 16, ks * 2 + aCh);
                uint32_t ah[4], al[4];
                LDSM4(ah[0], ah[1], ah[2], ah[3], Ah + aoff);
                LDSM4(al[0], al[1], al[2], al[3], Al + aoff);
                #pragma unroll
                for (int nf = 0; nf < 4; nf++) {
                    MMA16816(acc[mf][nf], ah, bh[nf]);
                    MMA16816(acc[mf][nf], ah, bl[nf]);
                    MMA16816(acc[mf][nf], al, bh[nf]);
                }
            }
        }
        if (++stg_idx == NSTAGE) stg_idx = 0;
    }

    int erow = m0 + wm * 64 + (lane >> 2);
    int ecol = n0 + wn * 32 + (lane & 3) * 2;
    #pragma unroll
    for (int mf = 0; mf < 4; mf++)
        #pragma unroll
        for (int nf = 0; nf < 4; nf++) {
            int col = ecol + nf * 8;
            #pragma unroll
            for (int half = 0; half < 2; half++) {
                int row = erow + mf * 16 + half * 8;
                float v0 = acc[mf][nf][half * 2 + 0];
                float v1 = acc[mf][nf][half * 2 + 1];
                if (col < 1024) {
                    *(float2*)(g_xin + row * D_MODEL + col) = make_float2(v0, v1);
                } else if (col < 1120) {
                    *(float2*)(g_proj + row * NPROJ + (col - 1024)) =
                        make_float2(v0, v1);
                }
            }
        }
}

// ---------------- K3: dt = softplus(dt_low @ w_dt + b_dt)*0.099+0.001 ------
// Plain version (no partials) — runs concurrent with main GEMM.
__global__ __launch_bounds__(256) void k_gemm_dt(
    const float* __restrict__ Wdt, const float* __restrict__ bdt) {
    __shared__ float As[64][68];
    __shared__ float Bs[64][64];
    int tid = threadIdx.x;
    int col0 = blockIdx.x * 64;
    int row0 = blockIdx.y * 64;

    #pragma unroll
    for (int q = 0; q < 16; q++) {
        int idx = tid + q * 256;
        int m = idx >> 6, kk = idx & 63;
        As[kk][m] = g_proj[(row0 + m) * NPROJ + kk];
    }
    #pragma unroll
    for (int q = 0; q < 16; q++) {
        int idx = tid + q * 256;
        int kk = idx >> 6, n = idx & 63;
        Bs[kk][n] = Wdt[kk * D_MODEL + col0 + n];
    }
    __syncthreads();

    int tm = tid >> 4, tn = tid & 15;
    float acc[4][4];
    #pragma unroll
    for (int i = 0; i < 4; i++)
        #pragma unroll
        for (int j = 0; j < 4; j++) acc[i][j] = 0.f;

    #pragma unroll 8
    for (int k = 0; k < 64; k++) {
        float4 ra = *(const float4*)&As[k][tm * 4];
        float4 rb = *(const float4*)&Bs[k][tn * 4];
        float a[4] = { ra.x, ra.y, ra.z, ra.w };
        float b[4] = { rb.x, rb.y, rb.z, rb.w };
        #pragma unroll
        for (int i = 0; i < 4; i++)
            #pragma unroll
            for (int j = 0; j < 4; j++) acc[i][j] += a[i] * b[j];
    }
    #pragma unroll
    for (int i = 0; i < 4; i++)
        #pragma unroll
        for (int j = 0; j < 4; j++) {
            int col = col0 + tn * 4 + j;
            float z = acc[i][j] + bdt[col];
            float sp = fmaxf(z, 0.f) + log1pf(__expf(-fabsf(z)));
            g_dt[(row0 + tm * 4 + i) * D_MODEL + col] = sp * 0.099f + 0.001f;
        }
}

// ---------------- K4: inp_term[r][n] = B[r][n] * sum_d dt*u*A[d][n] --------
// smem two-stage reduction (R10-proven).
__global__ __launch_bounds__(256) void k_inp() {
    __shared__ float sred[256][17];
    __shared__ float p2[16][17];
    int r = blockIdx.x;
    int tid = threadIdx.x;
    float acc[D_STATE];
    #pragma unroll
    for (int n = 0; n < D_STATE; n++) acc[n] = 0.f;

    const float* dtr = g_dt + r * D_MODEL;
    const float* ur  = g_xin + r * D_MODEL;
    #pragma unroll
    for (int q4 = 0; q4 < 4; q4++) {
        int d = tid + q4 * 256;
        float w = dtr[d] * ur[d];
        const float4* Ap = (const float4*)(g_A + d * D_STATE);
        #pragma unroll
        for (int q = 0; q < 4; q++) {
            float4 a = Ap[q];
            acc[q * 4 + 0] += w * a.x;
            acc[q * 4 + 1] += w * a.y;
            acc[q * 4 + 2] += w * a.z;
            acc[q * 4 + 3] += w * a.w;
        }
    }
    #pragma unroll
    for (int n = 0; n < D_STATE; n++) sred[tid][n] = acc[n];
    __syncthreads();

    int g = tid >> 4, n = tid & 15;
    float s = 0.f;
    #pragma unroll
    for (int rr = 0; rr < 16; rr++) s += sred[g * 16 + rr][n];
    p2[g][n] = s;
    __syncthreads();

    if (tid < D_STATE) {
        float tot = 0.f;
        #pragma unroll
        for (int g2 = 0; g2 < 16; g2++) tot += p2[g2][tid];
        float Bm = g_proj[r * NPROJ + DT_RANK + tid];
        g_inp[r * D_STATE + tid] = Bm * tot;
    }
}

// ---------------- K5: scan phase A -----------------------------------------
__global__ __launch_bounds__(256) void k_scanA() {
    int blk = blockIdx.x;
    int dgrp = blk & 3;
    int c = (blk >> 2) & (NC - 1);
    int b = blk >> 8;
    int d = dgrp * 256 + threadIdx.x;
    int rbase = b * SEQ + c * CT;

    __shared__ __align__(16) float s_inp[CT * D_STATE];
    if (threadIdx.x < 128)
        ((float4*)s_inp)[threadIdx.x] =
            ((const float4*)(g_inp + rbase * D_STATE))[threadIdx.x];
    __syncthreads();

    float Ar[D_STATE];
    {
        const float4* Ap = (const float4*)(g_A2 + d * D_STATE);
        #pragma unroll
        for (int q = 0; q < 4; q++) {
            float4 a = Ap[q];
            Ar[q*4+0]=a.x; Ar[q*4+1]=a.y; Ar[q*4+2]=a.z; Ar[q*4+3]=a.w;
        }
    }
    float h[D_STATE];
    #pragma unroll
    for (int n = 0; n < D_STATE; n++) h[n] = 0.f;
    float S = 0.f;

    const float* dtp = g_dt + rbase * D_MODEL + d;
    float dta = dtp[0];
    float dtb = dtp[D_MODEL];

    #pragma unroll 8
    for (int t = 0; t < CT; t++) {
        float cur = dta;
        dta = dtb;
        if (t + 2 < CT) dtb = dtp[(t + 2) * D_MODEL];
        S += cur;
        const float4* ip = (const float4*)(s_inp + t * D_STATE);
        float4 i0 = ip[0], i1 = ip[1], i2 = ip[2], i3 = ip[3];
        float inp[D_STATE] = { i0.x,i0.y,i0.z,i0.w, i1.x,i1.y,i1.z,i1.w,
                               i2.x,i2.y,i2.z,i2.w, i3.x,i3.y,i3.z,i3.w };
        #pragma unroll
        for (int n = 0; n < D_STATE; n++)
            h[n] = ex2(cur * Ar[n]) * h[n] + inp[n];
    }
    int base = (b * NC + c) * D_MODEL + d;
    g_S[base] = S;
    float* Lp = g_L + base * D_STATE;
    #pragma unroll
    for (int q = 0; q < 4; q++)
        ((float4*)Lp)[q] = make_float4(h[q*4+0], h[q*4+1], h[q*4+2], h[q*4+3]);
}

// ---------------- K6: scan phase B ------------------------------------------
__global__ __launch_bounds__(256) void k_scanB() {
    int idx = blockIdx.x * blockDim.x + threadIdx.x;
    int n = idx & (D_STATE - 1);
    int d = (idx >> 4) & (D_MODEL - 1);
    int b = idx >> 14;
    float a2 = g_A2[d * D_STATE + n];
    float hs = 0.f;
    #pragma unroll 4
    for (int c = 0; c < NC; c++) {
        int base = (b * NC + c) * D_MODEL + d;
        g_hs[base * D_STATE + n] = hs;
        hs = ex2(a2 * g_S[base]) * hs + g_L[base * D_STATE + n];
    }
}

// ---------------- K7: scan phase C ------------------------------------------
__global__ __launch_bounds__(256) void k_scanC(
    const float* __restrict__ Dp, float* __restrict__ out) {
    int blk = blockIdx.x;
    int dgrp = blk & 3;
    int c = (blk >> 2) & (NC - 1);
    int b = blk >> 8;
    int d = dgrp * 256 + threadIdx.x;
    int rbase = b * SEQ + c * CT;

    __shared__ __align__(16) float s_inp[CT * D_STATE];
    __shared__ __align__(16) float s_C[CT * D_STATE];
    if (threadIdx.x < 128) {
        ((float4*)s_inp)[threadIdx.x] =
            ((const float4*)(g_inp + rbase * D_STATE))[threadIdx.x];
        int t = threadIdx.x >> 2, c4 = threadIdx.x & 3;
        ((float4*)s_C)[threadIdx.x] =
            *(const float4*)(g_proj + (rbase + t) * NPROJ + DT_RANK + D_STATE + c4 * 4);
    }
    __syncthreads();

    float Ar[D_STATE], h[D_STATE];
    {
        const float4* Ap = (const float4*)(g_A2 + d * D_STATE);
        #pragma unroll
        for (int q = 0; q < 4; q++) {
            float4 a = Ap[q];
            Ar[q*4+0]=a.x; Ar[q*4+1]=a.y; Ar[q*4+2]=a.z; Ar[q*4+3]=a.w;
        }
        int base = (b * NC + c) * D_MODEL + d;
        const float4* Hp = (const float4*)(g_hs + base * D_STATE);
        #pragma unroll
        for (int q = 0; q < 4; q++) {
            float4 v = Hp[q];
            h[q*4+0]=v.x; h[q*4+1]=v.y; h[q*4+2]=v.z; h[q*4+3]=v.w;
        }
    }
    float dp = Dp[d];

    const float* dtp = g_dt + rbase * D_MODEL + d;
    const float* up  = g_xin + rbase * D_MODEL + d;
    float dta = dtp[0], dtb = dtp[D_MODEL];
    float ua  = up[0],  ub  = up[D_MODEL];

    #pragma unroll 8
    for (int t = 0; t < CT; t++) {
        float ldt = dta, u = ua;
        dta = dtb; ua = ub;
        if (t + 2 < CT) {
            dtb = dtp[(t + 2) * D_MODEL];
            ub  = up[(t + 2) * D_MODEL];
        }
        const float4* ip = (const float4*)(s_inp + t * D_STATE);
        const float4* cp = (const float4*)(s_C + t * D_STATE);
        float4 i0 = ip[0], i1 = ip[1], i2 = ip[2], i3 = ip[3];
        float4 c0 = cp[0], c1 = cp[1], c2 = cp[2], c3 = cp[3];
        float inp[D_STATE] = { i0.x,i0.y,i0.z,i0.w, i1.x,i1.y,i1.z,i1.w,
                               i2.x,i2.y,i2.z,i2.w, i3.x,i3.y,i3.z,i3.w };
        float cm[D_STATE]  = { c0.x,c0.y,c0.z,c0.w, c1.x,c1.y,c1.z,c1.w,
                               c2.x,c2.y,c2.z,c2.w, c3.x,c3.y,c3.z,c3.w };
        float y = dp * u;
        #pragma unroll
        for (int n = 0; n < D_STATE; n++) {
            h[n] = ex2(ldt * Ar[n]) * h[n] + inp[n];
            y += h[n] * cm[n];
        }
        __stcs(out + (rbase + t) * D_MODEL + d, y);
    }
}

// ---------------- launch ----------------------------------------------------
extern "C" void kernel_launch(void* const* d_in, const int* in_sizes, int n_in,
                              void* d_out, int out_size) {
    const float* x     = (const float*)d_in[0];
    const float* w_in  = (const float*)d_in[1];
    const float* w_x   = (const float*)d_in[2];
    const float* w_dt  = (const float*)d_in[3];
    const float* b_dt  = (const float*)d_in[4];
    const float* A_log = (const float*)d_in[5];
    const float* Dp    = (const float*)d_in[6];
    float* out = (float*)d_out;

    static cudaStream_t s2 = nullptr;
    static cudaEvent_t evFork = nullptr, evPrep = nullptr,
                       evReady = nullptr, evMain = nullptr;
    if (s2 == nullptr) {
        cudaStreamCreateWithFlags(&s2, cudaStreamNonBlocking);
        cudaEventCreateWithFlags(&evFork, cudaEventDisableTiming);
        cudaEventCreateWithFlags(&evPrep, cudaEventDisableTiming);
        cudaEventCreateWithFlags(&evReady, cudaEventDisableTiming);
        cudaEventCreateWithFlags(&evMain, cudaEventDisableTiming);
        cudaFuncSetAttribute(k_gemm_mma,
                             cudaFuncAttributeMaxDynamicSharedMemorySize,
                             GEMM_SMEM);
    }

    // fork: weight prep on s2, x conversion on stream 0
    cudaEventRecord(evFork, 0);
    cudaStreamWaitEvent(s2, evFork, 0);
    k_prep1<<<64, 256, 0, s2>>>(w_in, w_x);
    k_prep_w<<<dim3(NTOT / 32, D_MODEL / 32), dim3(32, 8), 0, s2>>>(w_in);
    cudaEventRecord(evPrep, s2);

    k_conv_x<<<(NROWS * D_MODEL) / 512, 256>>>(x, A_log);
    cudaStreamWaitEvent(0, evPrep, 0);
    cudaEventRecord(evReady, 0);
    cudaStreamWaitEvent(s2, evReady, 0);

    // main xin GEMM on s2 (cols 0..1023); proj-cols GEMM + dt chain on s0
    k_gemm_mma<<<dim3(8, NROWS / 128), 256, GEMM_SMEM, s2>>>(0);
    k_gemm_mma<<<dim3(1, NROWS / 128), 256, GEMM_SMEM, 0>>>(8);
    k_gemm_dt<<<dim3(D_MODEL / 64, NROWS / 64), 256>>>(w_dt, b_dt);
    cudaEventRecord(evMain, s2);
    cudaStreamWaitEvent(0, evMain, 0);

    k_inp<<<NROWS, 256>>>();
    k_scanA<<<NBATCH * NC * 4, 256>>>();
    k_scanB<<<NBATCH * D_MODEL * D_STATE / 256, 256>>>();
    k_scanC<<<NBATCH * NC * 4, 256>>>(Dp, out);
}

// round 14
// speedup vs baseline: 1.0177x; 1.0177x over previous
#include <cuda_runtime.h>
#include <cuda_bf16.h>
#include <cstdint>
#include <math.h>

#define D_MODEL 1024
#define D_STATE 16
#define DT_RANK 64
#define NBATCH 2
#define SEQ 2048
#define NROWS (NBATCH*SEQ)   // 4096
#define NPROJ 96
#define NC 64                // chunks per sequence
#define CT 32                // chunk length
#define NTOT 1152            // 1024 (w_in) + 96 (P) + 32 pad
#define NPART 16             // d-tiles producing inp partials

// ---------------- scratch (device globals) ---------------------------------
__device__ float g_xin [NROWS * D_MODEL];
__device__ float g_proj[NROWS * NPROJ];              // dt_low | B | C
__device__ float g_dt  [NROWS * D_MODEL];
__device__ float g_A   [D_MODEL * D_STATE];          // -exp(A_log)
__device__ float g_A2  [D_MODEL * D_STATE];          // -exp(A_log) * log2(e)
__device__ float g_inp [NROWS * D_STATE];
__device__ float g_inppart[NPART * NROWS * D_STATE]; // per-d-tile partials
__device__ float g_S   [NBATCH * NC * D_MODEL];
__device__ float g_L   [NBATCH * NC * D_MODEL * D_STATE];
__device__ float g_hs  [NBATCH * NC * D_MODEL * D_STATE];
// GEMM operands
__device__ __nv_bfloat16 g_xh [NROWS * D_MODEL];
__device__ __nv_bfloat16 g_xl [NROWS * D_MODEL];
__device__ __nv_bfloat16 g_wth[NTOT * D_MODEL];      // [w_in | P]^T hi  [n][k]
__device__ __nv_bfloat16 g_wtl[NTOT * D_MODEL];      // [w_in | P]^T lo  [n][k]
__device__ float g_P   [D_MODEL * NPROJ];            // w_in @ w_x

#define LOG2E 1.4426950408889634f

// ---------------- PTX helpers (family-portable) -----------------------------
__device__ __forceinline__ uint32_t smem_u32(const void* p) {
    uint32_t a;
    asm("{ .reg .u64 t; cvta.to.shared.u64 t, %1; cvt.u32.u64 %0, t; }"
        : "=r"(a) : "l"(p));
    return a;
}
__device__ __forceinline__ float ex2(float x) {
    float r;
    asm("ex2.approx.ftz.f32 %0, %1;" : "=f"(r) : "f"(x));
    return r;
}
__device__ __forceinline__ void cp16(uint32_t dst, const void* src) {
    asm volatile("cp.async.cg.shared.global [%0], [%1], 16;"
                 :: "r"(dst), "l"(src) : "memory");
}
#define CP_COMMIT() asm volatile("cp.async.commit_group;" ::: "memory")
#define CP_WAIT1()  asm volatile("cp.async.wait_group 1;" ::: "memory")
#define CP_WAIT0()  asm volatile("cp.async.wait_group 0;" ::: "memory")

#define LDSM4(r0,r1,r2,r3,addr) \
    asm volatile("ldmatrix.sync.aligned.m8n8.x4.shared.b16 {%0,%1,%2,%3}, [%4];" \
        : "=r"(r0),"=r"(r1),"=r"(r2),"=r"(r3) : "r"(addr))
#define LDSM2(r0,r1,addr) \
    asm volatile("ldmatrix.sync.aligned.m8n8.x2.shared.b16 {%0,%1}, [%2];" \
        : "=r"(r0),"=r"(r1) : "r"(addr))

#define MMA16816(d, a, b) \
    asm volatile("mma.sync.aligned.m16n8k16.row.col.f32.bf16.bf16.f32 " \
        "{%0,%1,%2,%3}, {%4,%5,%6,%7}, {%8,%9}, {%0,%1,%2,%3};" \
        : "+f"((d)[0]),"+f"((d)[1]),"+f"((d)[2]),"+f"((d)[3]) \
        : "r"((a)[0]),"r"((a)[1]),"r"((a)[2]),"r"((a)[3]), \
          "r"((b)[0]),"r"((b)[1]))

// ---------------- K_conv: split x into bf16 hi/lo (2-wide); A / A2 prep -----
__global__ __launch_bounds__(256) void k_conv_x(const float* __restrict__ x,
                                                const float* __restrict__ A_log) {
    int i = blockIdx.x * 256 + threadIdx.x;
    {
        float2 f = *(const float2*)(x + i * 2);
        __nv_bfloat16 h0 = __float2bfloat16(f.x);
        __nv_bfloat16 h1 = __float2bfloat16(f.y);
        __nv_bfloat162 hv; hv.x = h0; hv.y = h1;
        *(__nv_bfloat162*)(g_xh + i * 2) = hv;
        __nv_bfloat162 lv;
        lv.x = __float2bfloat16(f.x - __bfloat162float(h0));
        lv.y = __float2bfloat16(f.y - __bfloat162float(h1));
        *(__nv_bfloat162*)(g_xl + i * 2) = lv;
    }
    if (i < D_MODEL * D_STATE / 2) {
        float2 al = *(const float2*)(A_log + i * 2);
        float a0 = -__expf(al.x), a1 = -__expf(al.y);
        *(float2*)(g_A  + i * 2) = make_float2(a0, a1);
        *(float2*)(g_A2 + i * 2) = make_float2(a0 * LOG2E, a1 * LOG2E);
    }
}

// ---------------- K_prep1: P = w_in(1024x1024) @ w_x(1024x96) ---------------
__global__ __launch_bounds__(256) void k_prep1(const float* __restrict__ Win,
                                               const float* __restrict__ Wx) {
    __shared__ float As[32][16];
    __shared__ float Bs[32][96];
    int tid = threadIdx.x;
    int row0 = blockIdx.x * 16;
    int tm = tid >> 4, tn = tid & 15;
    float acc[6];
    #pragma unroll
    for (int j = 0; j < 6; j++) acc[j] = 0.f;

    for (int k0 = 0; k0 < D_MODEL; k0 += 32) {
        #pragma unroll
        for (int q = 0; q < 2; q++) {
            int idx = tid + q * 256;
            int m = idx >> 5, kk = idx & 31;
            As[kk][m] = Win[(row0 + m) * D_MODEL + k0 + kk];
        }
        #pragma unroll
        for (int q = 0; q < 3; q++) {
            int f4 = tid + q * 256;
            int kk = f4 / 24, cg = f4 % 24;
            float4 v = *(const float4*)(Wx + (k0 + kk) * NPROJ + cg * 4);
            *(float4*)&Bs[kk][cg * 4] = v;
        }
        __syncthreads();
        #pragma unroll
        for (int k = 0; k < 32; k++) {
            float a = As[k][tm];
            #pragma unroll
            for (int j = 0; j < 6; j++) acc[j] += a * Bs[k][tn * 6 + j];
        }
        __syncthreads();
    }
    #pragma unroll
    for (int j = 0; j < 6; j++)
        g_P[(row0 + tm) * NPROJ + tn * 6 + j] = acc[j];
}

// ---------------- K_prep_w: transpose+split [w_in | P | 0] -> hi/lo ---------
__global__ void k_prep_w(const float* __restrict__ Win) {
    __shared__ float t[32][33];
    int nb = blockIdx.x * 32, kb = blockIdx.y * 32;
    int tx = threadIdx.x, ty = threadIdx.y;
    int tid = ty * 32 + tx;
    #pragma unroll
    for (int i = 0; i < 32; i += 8) {
        int k = kb + ty + i, n = nb + tx;
        float v;
        if (n < 1024)      v = Win[k * D_MODEL + n];
        else if (n < 1120) v = g_P[k * NPROJ + (n - 1024)];
        else               v = 0.f;
        t[ty + i][tx] = v;
    }
    __syncthreads();
    #pragma unroll
    for (int q = 0; q < 2; q++) {
        int idx = tid + q * 256;
        int nn  = idx >> 4;
        int kk2 = (idx & 15) * 2;
        float f0 = t[kk2][nn], f1 = t[kk2 + 1][nn];
        __nv_bfloat16 h0 = __float2bfloat16(f0);
        __nv_bfloat16 h1 = __float2bfloat16(f1);
        __nv_bfloat162 hv; hv.x = h0; hv.y = h1;
        __nv_bfloat162 lv;
        lv.x = __float2bfloat16(f0 - __bfloat162float(h0));
        lv.y = __float2bfloat16(f1 - __bfloat162float(h1));
        int n = nb + nn, k = kb + kk2;
        *(__nv_bfloat162*)(g_wth + n * D_MODEL + k) = hv;
        *(__nv_bfloat162*)(g_wtl + n * D_MODEL + k) = lv;
    }
}

// ---------------- K1: mma GEMM x(4096x1024) @ [w_in|P](1024x1120) -----------
// Single grid (R8/R9-proven). 3-stage cp.async, swizzled, 2 CTAs/SM.
#define TILE_B (128 * 64)
#define STAGE_B (4 * TILE_B)
#define NSTAGE 3
#define GEMM_SMEM (NSTAGE * STAGE_B)
#define NT (D_MODEL / 32)

__device__ __forceinline__ uint32_t swz(int r, int c) {
    return (uint32_t)(r * 64 + ((c ^ ((r >> 1) & 3)) << 4));
}

__global__ __launch_bounds__(256, 2) void k_gemm_mma() {
    extern __shared__ char smem[];
    uint32_t sb = smem_u32(smem);
    int tid = threadIdx.x, wid = tid >> 5, lane = tid & 31;
    int n0 = blockIdx.x * 128, m0 = blockIdx.y * 128;
    int wm = wid >> 2, wn = wid & 3;

    const __nv_bfloat16* srcs[4] = {
        g_xh  + m0 * D_MODEL, g_xl  + m0 * D_MODEL,
        g_wth + n0 * D_MODEL, g_wtl + n0 * D_MODEL };

    int r0 = tid >> 2,        c0 = tid & 3;
    int r1 = (tid >> 2) + 64, c1 = tid & 3;
    uint32_t d0 = swz(r0, c0), d1 = swz(r1, c1);

    #pragma unroll
    for (int s = 0; s < 2; s++) {
        uint32_t stb = sb + s * STAGE_B;
        int k0 = s * 32;
        #pragma unroll
        for (int tk = 0; tk < 4; tk++) {
            cp16(stb + tk * TILE_B + d0, srcs[tk] + r0 * D_MODEL + k0 + c0 * 8);
            cp16(stb + tk * TILE_B + d1, srcs[tk] + r1 * D_MODEL + k0 + c1 * 8);
        }
        CP_COMMIT();
    }

    float acc[4][4][4];
    #pragma unroll
    for (int mf = 0; mf < 4; mf++)
        #pragma unroll
        for (int nf = 0; nf < 4; nf++)
            #pragma unroll
            for (int q = 0; q < 4; q++) acc[mf][nf][q] = 0.f;

    int aRow = wm * 64 + (lane & 15);
    int aCh  = lane >> 4;
    int bRow = wn * 32 + (lane & 7);
    int bCh  = (lane >> 3) & 1;

    int stg_idx = 0;
    for (int kt = 0; kt < NT; kt++) {
        if (kt + 1 < NT) CP_WAIT1(); else CP_WAIT0();
        __syncthreads();

        if (kt + 2 < NT) {
            int k0 = (kt + 2) * 32;
            int s = stg_idx + 2; if (s >= NSTAGE) s -= NSTAGE;
            uint32_t stb = sb + s * STAGE_B;
            #pragma unroll
            for (int tk = 0; tk < 4; tk++) {
                cp16(stb + tk * TILE_B + d0, srcs[tk] + r0 * D_MODEL + k0 + c0 * 8);
                cp16(stb + tk * TILE_B + d1, srcs[tk] + r1 * D_MODEL + k0 + c1 * 8);
            }
            CP_COMMIT();
        }

        uint32_t stg = sb + stg_idx * STAGE_B;
        uint32_t Ah = stg, Al = stg + TILE_B;
        uint32_t Bh = stg + 2 * TILE_B, Bl = stg + 3 * TILE_B;

        #pragma unroll
        for (int ks = 0; ks < 2; ks++) {
            uint32_t bh[4][2], bl[4][2];
            #pragma unroll
            for (int nf = 0; nf < 4; nf++) {
                uint32_t boff = swz(bRow + nf * 8, ks * 2 + bCh);
                LDSM2(bh[nf][0], bh[nf][1], Bh + boff);
                LDSM2(bl[nf][0], bl[nf][1], Bl + boff);
            }
            #pragma unroll
            for (int mf = 0; mf < 4; mf++) {
                uint32_t aoff = swz(aRow + mf * 16, ks * 2 + aCh);
                uint32_t ah[4], al[4];
                LDSM4(ah[0], ah[1], ah[2], ah[3], Ah + aoff);
                LDSM4(al[0], al[1], al[2], al[3], Al + aoff);
                #pragma unroll
                for (int nf = 0; nf < 4; nf++) {
                    MMA16816(acc[mf][nf], ah, bh[nf]);
                    MMA16816(acc[mf][nf], ah, bl[nf]);
                    MMA16816(acc[mf][nf], al, bh[nf]);
                }
            }
        }
        if (++stg_idx == NSTAGE) stg_idx = 0;
    }

    int erow = m0 + wm * 64 + (lane >> 2);
    int ecol = n0 + wn * 32 + (lane & 3) * 2;
    #pragma unroll
    for (int mf = 0; mf < 4; mf++)
        #pragma unroll
        for (int nf = 0; nf < 4; nf++) {
            int col = ecol + nf * 8;
            #pragma unroll
            for (int half = 0; half < 2; half++) {
                int row = erow + mf * 16 + half * 8;
                float v0 = acc[mf][nf][half * 2 + 0];
                float v1 = acc[mf][nf][half * 2 + 1];
                if (col < 1024) {
                    *(float2*)(g_xin + row * D_MODEL + col) = make_float2(v0, v1);
                } else if (col < 1120) {
                    *(float2*)(g_proj + row * NPROJ + (col - 1024)) =
                        make_float2(v0, v1);
                }
            }
        }
}

// ---------------- K3: dt GEMM (BM=128, 8x4 regs) + fused inp partials -------
// Emits g_inppart[bx][row][n] = sum_{d in tile} dt*u*A[d][n] (deterministic).
__global__ __launch_bounds__(256) void k_gemm_dt(
    const float* __restrict__ Wdt, const float* __restrict__ bdt) {
    __shared__ float As[64][128];        // As[k][row], broadcast reads
    __shared__ float Bs[64][64];
    __shared__ float sA[64][17];
    int tid = threadIdx.x;
    int col0 = blockIdx.x * 64;
    int row0 = blockIdx.y * 128;

    // As: 128 rows x 64 k, float4 loads from g_proj (row stride 96 floats)
    #pragma unroll
    for (int q = 0; q < 8; q++) {
        int f4 = tid + q * 256;          // 0..2047
        int m = f4 >> 4;                 // 0..127
        int kk = (f4 & 15) * 4;          // 0..60
        float4 v = *(const float4*)(g_proj + (row0 + m) * NPROJ + kk);
        As[kk + 0][m] = v.x; As[kk + 1][m] = v.y;
        As[kk + 2][m] = v.z; As[kk + 3][m] = v.w;
    }
    #pragma unroll
    for (int q = 0; q < 16; q++) {
        int idx = tid + q * 256;
        int kk = idx >> 6, n = idx & 63;
        Bs[kk][n] = Wdt[kk * D_MODEL + col0 + n];
    }
    #pragma unroll
    for (int q = 0; q < 4; q++) {
        int idx = tid + q * 256;
        int cc = idx >> 4, n = idx & 15;
        sA[cc][n] = g_A[(col0 + cc) * D_STATE + n];
    }
    __syncthreads();

    int tm = tid >> 4, tn = tid & 15;    // tm: 8-row group, tn: 4-col group
    float acc[8][4];
    #pragma unroll
    for (int i = 0; i < 8; i++)
        #pragma unroll
        for (int j = 0; j < 4; j++) acc[i][j] = 0.f;

    #pragma unroll 8
    for (int k = 0; k < 64; k++) {
        float4 ra0 = *(const float4*)&As[k][tm * 8];
        float4 ra1 = *(const float4*)&As[k][tm * 8 + 4];
        float4 rb  = *(const float4*)&Bs[k][tn * 4];
        float a[8] = { ra0.x, ra0.y, ra0.z, ra0.w, ra1.x, ra1.y, ra1.z, ra1.w };
        float b[4] = { rb.x, rb.y, rb.z, rb.w };
        #pragma unroll
        for (int i = 0; i < 8; i++)
            #pragma unroll
            for (int j = 0; j < 4; j++) acc[i][j] += a[i] * b[j];
    }

    float4 bv = *(const float4*)(bdt + col0 + tn * 4);
    float bb[4] = { bv.x, bv.y, bv.z, bv.w };

    #pragma unroll
    for (int i = 0; i < 8; i++) {
        int row = row0 + tm * 8 + i;
        float dtv[4];
        #pragma unroll
        for (int j = 0; j < 4; j++) {
            float z = acc[i][j] + bb[j];
            float sp = fmaxf(z, 0.f) + log1pf(__expf(-fabsf(z)));
            dtv[j] = sp * 0.099f + 0.001f;
        }
        *(float4*)(g_dt + row * D_MODEL + col0 + tn * 4) =
            make_float4(dtv[0], dtv[1], dtv[2], dtv[3]);

        float4 uv = *(const float4*)(g_xin + row * D_MODEL + col0 + tn * 4);
        float p[4] = { dtv[0]*uv.x, dtv[1]*uv.y, dtv[2]*uv.z, dtv[3]*uv.w };
        float part[D_STATE];
        #pragma unroll
        for (int n = 0; n < D_STATE; n++) {
            float s = 0.f;
            #pragma unroll
            for (int j = 0; j < 4; j++) s += p[j] * sA[tn * 4 + j][n];
            part[n] = s;
        }
        #pragma unroll
        for (int n = 0; n < D_STATE; n++) {
            #pragma unroll
            for (int off = 8; off > 0; off >>= 1)
                part[n] += __shfl_down_sync(0xFFFFFFFFu, part[n], off, 16);
        }
        if (tn == 0) {
            #pragma unroll
            for (int n = 0; n < D_STATE; n += 4)
                *(float4*)(g_inppart + (blockIdx.x * NROWS + row) * D_STATE + n) =
                    make_float4(part[n], part[n+1], part[n+2], part[n+3]);
        }
    }
}

// ---------------- K4: inp_sum — fold 16 partials, multiply by B -------------
__global__ __launch_bounds__(256) void k_inp_sum() {
    int idx = blockIdx.x * 256 + threadIdx.x;    // 0..65535
    int r = idx >> 4, n = idx & 15;
    float s = 0.f;
    #pragma unroll
    for (int p = 0; p < NPART; p++)
        s += g_inppart[(p * NROWS + r) * D_STATE + n];
    g_inp[idx] = s * g_proj[r * NPROJ + DT_RANK + n];
}

// ---------------- K5: scan phase A -----------------------------------------
__global__ __launch_bounds__(256) void k_scanA() {
    int blk = blockIdx.x;
    int dgrp = blk & 3;
    int c = (blk >> 2) & (NC - 1);
    int b = blk >> 8;
    int d = dgrp * 256 + threadIdx.x;
    int rbase = b * SEQ + c * CT;

    __shared__ __align__(16) float s_inp[CT * D_STATE];
    if (threadIdx.x < 128)
        ((float4*)s_inp)[threadIdx.x] =
            ((const float4*)(g_inp + rbase * D_STATE))[threadIdx.x];
    __syncthreads();

    float Ar[D_STATE];
    {
        const float4* Ap = (const float4*)(g_A2 + d * D_STATE);
        #pragma unroll
        for (int q = 0; q < 4; q++) {
            float4 a = Ap[q];
            Ar[q*4+0]=a.x; Ar[q*4+1]=a.y; Ar[q*4+2]=a.z; Ar[q*4+3]=a.w;
        }
    }
    float h[D_STATE];
    #pragma unroll
    for (int n = 0; n < D_STATE; n++) h[n] = 0.f;
    float S = 0.f;

    const float* dtp = g_dt + rbase * D_MODEL + d;
    float dta = dtp[0];
    float dtb = dtp[D_MODEL];

    #pragma unroll 8
    for (int t = 0; t < CT; t++) {
        float cur = dta;
        dta = dtb;
        if (t + 2 < CT) dtb = dtp[(t + 2) * D_MODEL];
        S += cur;
        const float4* ip = (const float4*)(s_inp + t * D_STATE);
        float4 i0 = ip[0], i1 = ip[1], i2 = ip[2], i3 = ip[3];
        float inp[D_STATE] = { i0.x,i0.y,i0.z,i0.w, i1.x,i1.y,i1.z,i1.w,
                               i2.x,i2.y,i2.z,i2.w, i3.x,i3.y,i3.z,i3.w };
        #pragma unroll
        for (int n = 0; n < D_STATE; n++)
            h[n] = ex2(cur * Ar[n]) * h[n] + inp[n];
    }
    int base = (b * NC + c) * D_MODEL + d;
    g_S[base] = S;
    float* Lp = g_L + base * D_STATE;
    #pragma unroll
    for (int q = 0; q < 4; q++)
        ((float4*)Lp)[q] = make_float4(h[q*4+0], h[q*4+1], h[q*4+2], h[q*4+3]);
}

// ---------------- K6: scan phase B ------------------------------------------
__global__ __launch_bounds__(256) void k_scanB() {
    int idx = blockIdx.x * blockDim.x + threadIdx.x;
    int n = idx & (D_STATE - 1);
    int d = (idx >> 4) & (D_MODEL - 1);
    int b = idx >> 14;
    float a2 = g_A2[d * D_STATE + n];
    float hs = 0.f;
    #pragma unroll 4
    for (int c = 0; c < NC; c++) {
        int base = (b * NC + c) * D_MODEL + d;
        g_hs[base * D_STATE + n] = hs;
        hs = ex2(a2 * g_S[base]) * hs + g_L[base * D_STATE + n];
    }
}

// ---------------- K7: scan phase C ------------------------------------------
__global__ __launch_bounds__(256) void k_scanC(
    const float* __restrict__ Dp, float* __restrict__ out) {
    int blk = blockIdx.x;
    int dgrp = blk & 3;
    int c = (blk >> 2) & (NC - 1);
    int b = blk >> 8;
    int d = dgrp * 256 + threadIdx.x;
    int rbase = b * SEQ + c * CT;

    __shared__ __align__(16) float s_inp[CT * D_STATE];
    __shared__ __align__(16) float s_C[CT * D_STATE];
    if (threadIdx.x < 128) {
        ((float4*)s_inp)[threadIdx.x] =
            ((const float4*)(g_inp + rbase * D_STATE))[threadIdx.x];
        int t = threadIdx.x >> 2, c4 = threadIdx.x & 3;
        ((float4*)s_C)[threadIdx.x] =
            *(const float4*)(g_proj + (rbase + t) * NPROJ + DT_RANK + D_STATE + c4 * 4);
    }
    __syncthreads();

    float Ar[D_STATE], h[D_STATE];
    {
        const float4* Ap = (const float4*)(g_A2 + d * D_STATE);
        #pragma unroll
        for (int q = 0; q < 4; q++) {
            float4 a = Ap[q];
            Ar[q*4+0]=a.x; Ar[q*4+1]=a.y; Ar[q*4+2]=a.z; Ar[q*4+3]=a.w;
        }
        int base = (b * NC + c) * D_MODEL + d;
        const float4* Hp = (const float4*)(g_hs + base * D_STATE);
        #pragma unroll
        for (int q = 0; q < 4; q++) {
            float4 v = Hp[q];
            h[q*4+0]=v.x; h[q*4+1]=v.y; h[q*4+2]=v.z; h[q*4+3]=v.w;
        }
    }
    float dp = Dp[d];

    const float* dtp = g_dt + rbase * D_MODEL + d;
    const float* up  = g_xin + rbase * D_MODEL + d;
    float dta = dtp[0], dtb = dtp[D_MODEL];
    float ua  = up[0],  ub  = up[D_MODEL];

    #pragma unroll 8
    for (int t = 0; t < CT; t++) {
        float ldt = dta, u = ua;
        dta = dtb; ua = ub;
        if (t + 2 < CT) {
            dtb = dtp[(t + 2) * D_MODEL];
            ub  = up[(t + 2) * D_MODEL];
        }
        const float4* ip = (const float4*)(s_inp + t * D_STATE);
        const float4* cp = (const float4*)(s_C + t * D_STATE);
        float4 i0 = ip[0], i1 = ip[1], i2 = ip[2], i3 = ip[3];
        float4 c0 = cp[0], c1 = cp[1], c2 = cp[2], c3 = cp[3];
        float inp[D_STATE] = { i0.x,i0.y,i0.z,i0.w, i1.x,i1.y,i1.z,i1.w,
                               i2.x,i2.y,i2.z,i2.w, i3.x,i3.y,i3.z,i3.w };
        float cm[D_STATE]  = { c0.x,c0.y,c0.z,c0.w, c1.x,c1.y,c1.z,c1.w,
                               c2.x,c2.y,c2.z,c2.w, c3.x,c3.y,c3.z,c3.w };
        float y = dp * u;
        #pragma unroll
        for (int n = 0; n < D_STATE; n++) {
            h[n] = ex2(ldt * Ar[n]) * h[n] + inp[n];
            y += h[n] * cm[n];
        }
        __stcs(out + (rbase + t) * D_MODEL + d, y);
    }
}

// ---------------- launch (R11 schedule) -------------------------------------
extern "C" void kernel_launch(void* const* d_in, const int* in_sizes, int n_in,
                              void* d_out, int out_size) {
    const float* x     = (const float*)d_in[0];
    const float* w_in  = (const float*)d_in[1];
    const float* w_x   = (const float*)d_in[2];
    const float* w_dt  = (const float*)d_in[3];
    const float* b_dt  = (const float*)d_in[4];
    const float* A_log = (const float*)d_in[5];
    const float* Dp    = (const float*)d_in[6];
    float* out = (float*)d_out;

    static cudaStream_t s2 = nullptr;
    static cudaEvent_t evFork = nullptr, evJoin = nullptr;
    if (s2 == nullptr) {
        cudaStreamCreateWithFlags(&s2, cudaStreamNonBlocking);
        cudaEventCreateWithFlags(&evFork, cudaEventDisableTiming);
        cudaEventCreateWithFlags(&evJoin, cudaEventDisableTiming);
        cudaFuncSetAttribute(k_gemm_mma,
                             cudaFuncAttributeMaxDynamicSharedMemorySize,
                             GEMM_SMEM);
    }

    // fork: weight-prep chain on s2, x-conversion on stream 0
    cudaEventRecord(evFork, 0);
    cudaStreamWaitEvent(s2, evFork, 0);
    k_prep1<<<64, 256, 0, s2>>>(w_in, w_x);
    k_prep_w<<<dim3(NTOT / 32, D_MODEL / 32), dim3(32, 8), 0, s2>>>(w_in);
    cudaEventRecord(evJoin, s2);

    k_conv_x<<<(NROWS * D_MODEL) / 512, 256>>>(x, A_log);
    cudaStreamWaitEvent(0, evJoin, 0);

    k_gemm_mma<<<dim3(NTOT / 128, NROWS / 128), 256, GEMM_SMEM>>>();
    k_gemm_dt<<<dim3(D_MODEL / 64, NROWS / 128), 256>>>(w_dt, b_dt);
    k_inp_sum<<<NROWS * D_STATE / 256, 256>>>();
    k_scanA<<<NBATCH * NC * 4, 256>>>();
    k_scanB<<<NBATCH * D_MODEL * D_STATE / 256, 256>>>();
    k_scanC<<<NBATCH * NC * 4, 256>>>(Dp, out);
}

// round 16
// speedup vs baseline: 1.0592x; 1.0407x over previous
#include <cuda_runtime.h>
#include <cuda_bf16.h>
#include <cstdint>
#include <math.h>

#define D_MODEL 1024
#define D_STATE 16
#define DT_RANK 64
#define NBATCH 2
#define SEQ 2048
#define NROWS (NBATCH*SEQ)   // 4096
#define NPROJ 96
#define NC 64                // chunks per sequence
#define CT 32                // chunk length
#define NTOT 1152            // 1024 (w_in) + 96 (P) + 32 pad
#define NPART 16             // d-tiles producing inp partials

// ---------------- scratch (device globals) ---------------------------------
__device__ float g_xin [NROWS * D_MODEL];
__device__ float g_proj[NROWS * NPROJ];              // dt_low | B | C
__device__ float g_dt  [NROWS * D_MODEL];
__device__ float g_A   [D_MODEL * D_STATE];          // -exp(A_log)
__device__ float g_A2  [D_MODEL * D_STATE];          // -exp(A_log) * log2(e)
__device__ float g_inp [NROWS * D_STATE];
__device__ float g_inppart[NPART * NROWS * D_STATE]; // per-d-tile partials
__device__ float g_S   [NBATCH * NC * D_MODEL];
__device__ float g_L   [NBATCH * NC * D_MODEL * D_STATE];
__device__ float g_hs  [NBATCH * NC * D_MODEL * D_STATE];
// GEMM operands
__device__ __nv_bfloat16 g_xh [NROWS * D_MODEL];
__device__ __nv_bfloat16 g_xl [NROWS * D_MODEL];
__device__ __nv_bfloat16 g_wth[NTOT * D_MODEL];      // [w_in | P]^T hi  [n][k]
__device__ __nv_bfloat16 g_wtl[NTOT * D_MODEL];      // [w_in | P]^T lo  [n][k]
__device__ float g_P   [D_MODEL * NPROJ];            // w_in @ w_x

#define LOG2E 1.4426950408889634f

// ---------------- PTX helpers (family-portable) -----------------------------
__device__ __forceinline__ uint32_t smem_u32(const void* p) {
    uint32_t a;
    asm("{ .reg .u64 t; cvta.to.shared.u64 t, %1; cvt.u32.u64 %0, t; }"
        : "=r"(a) : "l"(p));
    return a;
}
__device__ __forceinline__ float ex2(float x) {
    float r;
    asm("ex2.approx.ftz.f32 %0, %1;" : "=f"(r) : "f"(x));
    return r;
}
__device__ __forceinline__ void cp16(uint32_t dst, const void* src) {
    asm volatile("cp.async.cg.shared.global [%0], [%1], 16;"
                 :: "r"(dst), "l"(src) : "memory");
}
#define CP_COMMIT() asm volatile("cp.async.commit_group;" ::: "memory")
#define CP_WAIT1()  asm volatile("cp.async.wait_group 1;" ::: "memory")
#define CP_WAIT0()  asm volatile("cp.async.wait_group 0;" ::: "memory")

#define LDSM4(r0,r1,r2,r3,addr) \
    asm volatile("ldmatrix.sync.aligned.m8n8.x4.shared.b16 {%0,%1,%2,%3}, [%4];" \
        : "=r"(r0),"=r"(r1),"=r"(r2),"=r"(r3) : "r"(addr))
#define LDSM2(r0,r1,addr) \
    asm volatile("ldmatrix.sync.aligned.m8n8.x2.shared.b16 {%0,%1}, [%2];" \
        : "=r"(r0),"=r"(r1) : "r"(addr))

#define MMA16816(d, a, b) \
    asm volatile("mma.sync.aligned.m16n8k16.row.col.f32.bf16.bf16.f32 " \
        "{%0,%1,%2,%3}, {%4,%5,%6,%7}, {%8,%9}, {%0,%1,%2,%3};" \
        : "+f"((d)[0]),"+f"((d)[1]),"+f"((d)[2]),"+f"((d)[3]) \
        : "r"((a)[0]),"r"((a)[1]),"r"((a)[2]),"r"((a)[3]), \
          "r"((b)[0]),"r"((b)[1]))

// ---------------- K_conv: split x into bf16 hi/lo (2-wide); A / A2 prep -----
__global__ __launch_bounds__(256) void k_conv_x(const float* __restrict__ x,
                                                const float* __restrict__ A_log) {
    int i = blockIdx.x * 256 + threadIdx.x;
    {
        float2 f = *(const float2*)(x + i * 2);
        __nv_bfloat16 h0 = __float2bfloat16(f.x);
        __nv_bfloat16 h1 = __float2bfloat16(f.y);
        __nv_bfloat162 hv; hv.x = h0; hv.y = h1;
        *(__nv_bfloat162*)(g_xh + i * 2) = hv;
        __nv_bfloat162 lv;
        lv.x = __float2bfloat16(f.x - __bfloat162float(h0));
        lv.y = __float2bfloat16(f.y - __bfloat162float(h1));
        *(__nv_bfloat162*)(g_xl + i * 2) = lv;
    }
    if (i < D_MODEL * D_STATE / 2) {
        float2 al = *(const float2*)(A_log + i * 2);
        float a0 = -__expf(al.x), a1 = -__expf(al.y);
        *(float2*)(g_A  + i * 2) = make_float2(a0, a1);
        *(float2*)(g_A2 + i * 2) = make_float2(a0 * LOG2E, a1 * LOG2E);
    }
}

// ---------------- K_prep1: P = w_in(1024x1024) @ w_x(1024x96) ---------------
__global__ __launch_bounds__(256) void k_prep1(const float* __restrict__ Win,
                                               const float* __restrict__ Wx) {
    __shared__ float As[32][16];
    __shared__ float Bs[32][96];
    int tid = threadIdx.x;
    int row0 = blockIdx.x * 16;
    int tm = tid >> 4, tn = tid & 15;
    float acc[6];
    #pragma unroll
    for (int j = 0; j < 6; j++) acc[j] = 0.f;

    for (int k0 = 0; k0 < D_MODEL; k0 += 32) {
        #pragma unroll
        for (int q = 0; q < 2; q++) {
            int idx = tid + q * 256;
            int m = idx >> 5, kk = idx & 31;
            As[kk][m] = Win[(row0 + m) * D_MODEL + k0 + kk];
        }
        #pragma unroll
        for (int q = 0; q < 3; q++) {
            int f4 = tid + q * 256;
            int kk = f4 / 24, cg = f4 % 24;
            float4 v = *(const float4*)(Wx + (k0 + kk) * NPROJ + cg * 4);
            *(float4*)&Bs[kk][cg * 4] = v;
        }
        __syncthreads();
        #pragma unroll
        for (int k = 0; k < 32; k++) {
            float a = As[k][tm];
            #pragma unroll
            for (int j = 0; j < 6; j++) acc[j] += a * Bs[k][tn * 6 + j];
        }
        __syncthreads();
    }
    #pragma unroll
    for (int j = 0; j < 6; j++)
        g_P[(row0 + tm) * NPROJ + tn * 6 + j] = acc[j];
}

// ---------------- K_prep_w: transpose+split [w_in | P | 0] -> hi/lo ---------
__global__ void k_prep_w(const float* __restrict__ Win) {
    __shared__ float t[32][33];
    int nb = blockIdx.x * 32, kb = blockIdx.y * 32;
    int tx = threadIdx.x, ty = threadIdx.y;
    int tid = ty * 32 + tx;
    #pragma unroll
    for (int i = 0; i < 32; i += 8) {
        int k = kb + ty + i, n = nb + tx;
        float v;
        if (n < 1024)      v = Win[k * D_MODEL + n];
        else if (n < 1120) v = g_P[k * NPROJ + (n - 1024)];
        else               v = 0.f;
        t[ty + i][tx] = v;
    }
    __syncthreads();
    #pragma unroll
    for (int q = 0; q < 2; q++) {
        int idx = tid + q * 256;
        int nn  = idx >> 4;
        int kk2 = (idx & 15) * 2;
        float f0 = t[kk2][nn], f1 = t[kk2 + 1][nn];
        __nv_bfloat16 h0 = __float2bfloat16(f0);
        __nv_bfloat16 h1 = __float2bfloat16(f1);
        __nv_bfloat162 hv; hv.x = h0; hv.y = h1;
        __nv_bfloat162 lv;
        lv.x = __float2bfloat16(f0 - __bfloat162float(h0));
        lv.y = __float2bfloat16(f1 - __bfloat162float(h1));
        int n = nb + nn, k = kb + kk2;
        *(__nv_bfloat162*)(g_wth + n * D_MODEL + k) = hv;
        *(__nv_bfloat162*)(g_wtl + n * D_MODEL + k) = lv;
    }
}

// ---------------- K1: mma GEMM x(4096x1024) @ [w_in|P](1024x1120) -----------
#define TILE_B (128 * 64)
#define STAGE_B (4 * TILE_B)
#define NSTAGE 3
#define GEMM_SMEM (NSTAGE * STAGE_B)
#define NT (D_MODEL / 32)

__device__ __forceinline__ uint32_t swz(int r, int c) {
    return (uint32_t)(r * 64 + ((c ^ ((r >> 1) & 3)) << 4));
}

__global__ __launch_bounds__(256, 2) void k_gemm_mma() {
    extern __shared__ char smem[];
    uint32_t sb = smem_u32(smem);
    int tid = threadIdx.x, wid = tid >> 5, lane = tid & 31;
    int n0 = blockIdx.x * 128, m0 = blockIdx.y * 128;
    int wm = wid >> 2, wn = wid & 3;

    const __nv_bfloat16* srcs[4] = {
        g_xh  + m0 * D_MODEL, g_xl  + m0 * D_MODEL,
        g_wth + n0 * D_MODEL, g_wtl + n0 * D_MODEL };

    int r0 = tid >> 2,        c0 = tid & 3;
    int r1 = (tid >> 2) + 64, c1 = tid & 3;
    uint32_t d0 = swz(r0, c0), d1 = swz(r1, c1);

    #pragma unroll
    for (int s = 0; s < 2; s++) {
        uint32_t stb = sb + s * STAGE_B;
        int k0 = s * 32;
        #pragma unroll
        for (int tk = 0; tk < 4; tk++) {
            cp16(stb + tk * TILE_B + d0, srcs[tk] + r0 * D_MODEL + k0 + c0 * 8);
            cp16(stb + tk * TILE_B + d1, srcs[tk] + r1 * D_MODEL + k0 + c1 * 8);
        }
        CP_COMMIT();
    }

    float acc[4][4][4];
    #pragma unroll
    for (int mf = 0; mf < 4; mf++)
        #pragma unroll
        for (int nf = 0; nf < 4; nf++)
            #pragma unroll
            for (int q = 0; q < 4; q++) acc[mf][nf][q] = 0.f;

    int aRow = wm * 64 + (lane & 15);
    int aCh  = lane >> 4;
    int bRow = wn * 32 + (lane & 7);
    int bCh  = (lane >> 3) & 1;

    int stg_idx = 0;
    for (int kt = 0; kt < NT; kt++) {
        if (kt + 1 < NT) CP_WAIT1(); else CP_WAIT0();
        __syncthreads();

        if (kt + 2 < NT) {
            int k0 = (kt + 2) * 32;
            int s = stg_idx + 2; if (s >= NSTAGE) s -= NSTAGE;
            uint32_t stb = sb + s * STAGE_B;
            #pragma unroll
            for (int tk = 0; tk < 4; tk++) {
                cp16(stb + tk * TILE_B + d0, srcs[tk] + r0 * D_MODEL + k0 + c0 * 8);
                cp16(stb + tk * TILE_B + d1, srcs[tk] + r1 * D_MODEL + k0 + c1 * 8);
            }
            CP_COMMIT();
        }

        uint32_t stg = sb + stg_idx * STAGE_B;
        uint32_t Ah = stg, Al = stg + TILE_B;
        uint32_t Bh = stg + 2 * TILE_B, Bl = stg + 3 * TILE_B;

        #pragma unroll
        for (int ks = 0; ks < 2; ks++) {
            uint32_t bh[4][2], bl[4][2];
            #pragma unroll
            for (int nf = 0; nf < 4; nf++) {
                uint32_t boff = swz(bRow + nf * 8, ks * 2 + bCh);
                LDSM2(bh[nf][0], bh[nf][1], Bh + boff);
                LDSM2(bl[nf][0], bl[nf][1], Bl + boff);
            }
            #pragma unroll
            for (int mf = 0; mf < 4; mf++) {
                uint32_t aoff = swz(aRow + mf * 16, ks * 2 + aCh);
                uint32_t ah[4], al[4];
                LDSM4(ah[0], ah[1], ah[2], ah[3], Ah + aoff);
                LDSM4(al[0], al[1], al[2], al[3], Al + aoff);
                #pragma unroll
                for (int nf = 0; nf < 4; nf++) {
                    MMA16816(acc[mf][nf], ah, bh[nf]);
                    MMA16816(acc[mf][nf], ah, bl[nf]);
                    MMA16816(acc[mf][nf], al, bh[nf]);
                }
            }
        }
        if (++stg_idx == NSTAGE) stg_idx = 0;
    }

    int erow = m0 + wm * 64 + (lane >> 2);
    int ecol = n0 + wn * 32 + (lane & 3) * 2;
    #pragma unroll
    for (int mf = 0; mf < 4; mf++)
        #pragma unroll
        for (int nf = 0; nf < 4; nf++) {
            int col = ecol + nf * 8;
            #pragma unroll
            for (int half = 0; half < 2; half++) {
                int row = erow + mf * 16 + half * 8;
                float v0 = acc[mf][nf][half * 2 + 0];
                float v1 = acc[mf][nf][half * 2 + 1];
                if (col < 1024) {
                    *(float2*)(g_xin + row * D_MODEL + col) = make_float2(v0, v1);
                } else if (col < 1120) {
                    *(float2*)(g_proj + row * NPROJ + (col - 1024)) =
                        make_float2(v0, v1);
                }
            }
        }
}

// ---------------- K3: dt GEMM (R11 version) + fused inp partials ------------
// rbase selects the batch's row range.
__global__ __launch_bounds__(256) void k_gemm_dt(
    const float* __restrict__ Wdt, const float* __restrict__ bdt, int rbase) {
    __shared__ float As[64][68];
    __shared__ float Bs[64][64];
    __shared__ float sA[64][17];
    int tid = threadIdx.x;
    int col0 = blockIdx.x * 64;
    int row0 = rbase + blockIdx.y * 64;

    #pragma unroll
    for (int q = 0; q < 16; q++) {
        int idx = tid + q * 256;
        int m = idx >> 6, kk = idx & 63;
        As[kk][m] = g_proj[(row0 + m) * NPROJ + kk];
    }
    #pragma unroll
    for (int q = 0; q < 16; q++) {
        int idx = tid + q * 256;
        int kk = idx >> 6, n = idx & 63;
        Bs[kk][n] = Wdt[kk * D_MODEL + col0 + n];
    }
    #pragma unroll
    for (int q = 0; q < 4; q++) {
        int idx = tid + q * 256;
        int cc = idx >> 4, n = idx & 15;
        sA[cc][n] = g_A[(col0 + cc) * D_STATE + n];
    }
    __syncthreads();

    int tm = tid >> 4, tn = tid & 15;
    float acc[4][4];
    #pragma unroll
    for (int i = 0; i < 4; i++)
        #pragma unroll
        for (int j = 0; j < 4; j++) acc[i][j] = 0.f;

    #pragma unroll 8
    for (int k = 0; k < 64; k++) {
        float4 ra = *(const float4*)&As[k][tm * 4];
        float4 rb = *(const float4*)&Bs[k][tn * 4];
        float a[4] = { ra.x, ra.y, ra.z, ra.w };
        float b[4] = { rb.x, rb.y, rb.z, rb.w };
        #pragma unroll
        for (int i = 0; i < 4; i++)
            #pragma unroll
            for (int j = 0; j < 4; j++) acc[i][j] += a[i] * b[j];
    }

    #pragma unroll
    for (int i = 0; i < 4; i++) {
        int row = row0 + tm * 4 + i;
        float dtv[4];
        #pragma unroll
        for (int j = 0; j < 4; j++) {
            int col = col0 + tn * 4 + j;
            float z = acc[i][j] + bdt[col];
            float sp = fmaxf(z, 0.f) + log1pf(__expf(-fabsf(z)));
            dtv[j] = sp * 0.099f + 0.001f;
        }
        *(float4*)(g_dt + row * D_MODEL + col0 + tn * 4) =
            make_float4(dtv[0], dtv[1], dtv[2], dtv[3]);

        float4 uv = *(const float4*)(g_xin + row * D_MODEL + col0 + tn * 4);
        float p[4] = { dtv[0]*uv.x, dtv[1]*uv.y, dtv[2]*uv.z, dtv[3]*uv.w };
        float part[D_STATE];
        #pragma unroll
        for (int n = 0; n < D_STATE; n++) {
            float s = 0.f;
            #pragma unroll
            for (int j = 0; j < 4; j++) s += p[j] * sA[tn * 4 + j][n];
            part[n] = s;
        }
        #pragma unroll
        for (int n = 0; n < D_STATE; n++) {
            #pragma unroll
            for (int off = 8; off > 0; off >>= 1)
                part[n] += __shfl_down_sync(0xFFFFFFFFu, part[n], off, 16);
        }
        if (tn == 0) {
            #pragma unroll
            for (int n = 0; n < D_STATE; n += 4)
                *(float4*)(g_inppart + (blockIdx.x * NROWS + row) * D_STATE + n) =
                    make_float4(part[n], part[n+1], part[n+2], part[n+3]);
        }
    }
}

// ---------------- K4: inp_sum — fold 16 partials, multiply by B -------------
__global__ __launch_bounds__(256) void k_inp_sum(int rbase) {
    int idx = blockIdx.x * 256 + threadIdx.x;    // 0..32767 (per batch)
    int r = rbase + (idx >> 4), n = idx & 15;
    float s = 0.f;
    #pragma unroll
    for (int p = 0; p < NPART; p++)
        s += g_inppart[(p * NROWS + r) * D_STATE + n];
    g_inp[r * D_STATE + n] = s * g_proj[r * NPROJ + DT_RANK + n];
}

// ---------------- K5: scan phase A (per batch) ------------------------------
__global__ __launch_bounds__(256) void k_scanA(int b) {
    int blk = blockIdx.x;                 // 0..255
    int dgrp = blk & 3;
    int c = blk >> 2;                     // 0..63
    int d = dgrp * 256 + threadIdx.x;
    int rbase = b * SEQ + c * CT;

    __shared__ __align__(16) float s_inp[CT * D_STATE];
    if (threadIdx.x < 128)
        ((float4*)s_inp)[threadIdx.x] =
            ((const float4*)(g_inp + rbase * D_STATE))[threadIdx.x];
    __syncthreads();

    float Ar[D_STATE];
    {
        const float4* Ap = (const float4*)(g_A2 + d * D_STATE);
        #pragma unroll
        for (int q = 0; q < 4; q++) {
            float4 a = Ap[q];
            Ar[q*4+0]=a.x; Ar[q*4+1]=a.y; Ar[q*4+2]=a.z; Ar[q*4+3]=a.w;
        }
    }
    float h[D_STATE];
    #pragma unroll
    for (int n = 0; n < D_STATE; n++) h[n] = 0.f;
    float S = 0.f;

    const float* dtp = g_dt + rbase * D_MODEL + d;
    float dta = dtp[0];
    float dtb = dtp[D_MODEL];

    #pragma unroll 8
    for (int t = 0; t < CT; t++) {
        float cur = dta;
        dta = dtb;
        if (t + 2 < CT) dtb = dtp[(t + 2) * D_MODEL];
        S += cur;
        const float4* ip = (const float4*)(s_inp + t * D_STATE);
        float4 i0 = ip[0], i1 = ip[1], i2 = ip[2], i3 = ip[3];
        float inp[D_STATE] = { i0.x,i0.y,i0.z,i0.w, i1.x,i1.y,i1.z,i1.w,
                               i2.x,i2.y,i2.z,i2.w, i3.x,i3.y,i3.z,i3.w };
        #pragma unroll
        for (int n = 0; n < D_STATE; n++)
            h[n] = ex2(cur * Ar[n]) * h[n] + inp[n];
    }
    int base = (b * NC + c) * D_MODEL + d;
    g_S[base] = S;
    float* Lp = g_L + base * D_STATE;
    #pragma unroll
    for (int q = 0; q < 4; q++)
        ((float4*)Lp)[q] = make_float4(h[q*4+0], h[q*4+1], h[q*4+2], h[q*4+3]);
}

// ---------------- K6: scan phase B (per batch) ------------------------------
__global__ __launch_bounds__(256) void k_scanB(int b) {
    int idx = blockIdx.x * blockDim.x + threadIdx.x;   // 0..16383
    int n = idx & (D_STATE - 1);
    int d = idx >> 4;
    float a2 = g_A2[d * D_STATE + n];
    float hs = 0.f;
    #pragma unroll 4
    for (int c = 0; c < NC; c++) {
        int base = (b * NC + c) * D_MODEL + d;
        g_hs[base * D_STATE + n] = hs;
        hs = ex2(a2 * g_S[base]) * hs + g_L[base * D_STATE + n];
    }
}

// ---------------- K7: scan phase C (per batch) ------------------------------
__global__ __launch_bounds__(256) void k_scanC(
    const float* __restrict__ Dp, float* __restrict__ out, int b) {
    int blk = blockIdx.x;                 // 0..255
    int dgrp = blk & 3;
    int c = blk >> 2;
    int d = dgrp * 256 + threadIdx.x;
    int rbase = b * SEQ + c * CT;

    __shared__ __align__(16) float s_inp[CT * D_STATE];
    __shared__ __align__(16) float s_C[CT * D_STATE];
    if (threadIdx.x < 128) {
        ((float4*)s_inp)[threadIdx.x] =
            ((const float4*)(g_inp + rbase * D_STATE))[threadIdx.x];
        int t = threadIdx.x >> 2, c4 = threadIdx.x & 3;
        ((float4*)s_C)[threadIdx.x] =
            *(const float4*)(g_proj + (rbase + t) * NPROJ + DT_RANK + D_STATE + c4 * 4);
    }
    __syncthreads();

    float Ar[D_STATE], h[D_STATE];
    {
        const float4* Ap = (const float4*)(g_A2 + d * D_STATE);
        #pragma unroll
        for (int q = 0; q < 4; q++) {
            float4 a = Ap[q];
            Ar[q*4+0]=a.x; Ar[q*4+1]=a.y; Ar[q*4+2]=a.z; Ar[q*4+3]=a.w;
        }
        int base = (b * NC + c) * D_MODEL + d;
        const float4* Hp = (const float4*)(g_hs + base * D_STATE);
        #pragma unroll
        for (int q = 0; q < 4; q++) {
            float4 v = Hp[q];
            h[q*4+0]=v.x; h[q*4+1]=v.y; h[q*4+2]=v.z; h[q*4+3]=v.w;
        }
    }
    float dp = Dp[d];

    const float* dtp = g_dt + rbase * D_MODEL + d;
    const float* up  = g_xin + rbase * D_MODEL + d;
    float dta = dtp[0], dtb = dtp[D_MODEL];
    float ua  = up[0],  ub  = up[D_MODEL];

    #pragma unroll 8
    for (int t = 0; t < CT; t++) {
        float ldt = dta, u = ua;
        dta = dtb; ua = ub;
        if (t + 2 < CT) {
            dtb = dtp[(t + 2) * D_MODEL];
            ub  = up[(t + 2) * D_MODEL];
        }
        const float4* ip = (const float4*)(s_inp + t * D_STATE);
        const float4* cp = (const float4*)(s_C + t * D_STATE);
        float4 i0 = ip[0], i1 = ip[1], i2 = ip[2], i3 = ip[3];
        float4 c0 = cp[0], c1 = cp[1], c2 = cp[2], c3 = cp[3];
        float inp[D_STATE] = { i0.x,i0.y,i0.z,i0.w, i1.x,i1.y,i1.z,i1.w,
                               i2.x,i2.y,i2.z,i2.w, i3.x,i3.y,i3.z,i3.w };
        float cm[D_STATE]  = { c0.x,c0.y,c0.z,c0.w, c1.x,c1.y,c1.z,c1.w,
                               c2.x,c2.y,c2.z,c2.w, c3.x,c3.y,c3.z,c3.w };
        float y = dp * u;
        #pragma unroll
        for (int n = 0; n < D_STATE; n++) {
            h[n] = ex2(ldt * Ar[n]) * h[n] + inp[n];
            y += h[n] * cm[n];
        }
        __stcs(out + (rbase + t) * D_MODEL + d, y);
    }
}

// ---------------- launch -----------------------------------------------------
extern "C" void kernel_launch(void* const* d_in, const int* in_sizes, int n_in,
                              void* d_out, int out_size) {
    const float* x     = (const float*)d_in[0];
    const float* w_in  = (const float*)d_in[1];
    const float* w_x   = (const float*)d_in[2];
    const float* w_dt  = (const float*)d_in[3];
    const float* b_dt  = (const float*)d_in[4];
    const float* A_log = (const float*)d_in[5];
    const float* Dp    = (const float*)d_in[6];
    float* out = (float*)d_out;

    static cudaStream_t s2 = nullptr;
    static cudaEvent_t evFork = nullptr, evJoin = nullptr,
                       evG = nullptr, evTail = nullptr;
    if (s2 == nullptr) {
        cudaStreamCreateWithFlags(&s2, cudaStreamNonBlocking);
        cudaEventCreateWithFlags(&evFork, cudaEventDisableTiming);
        cudaEventCreateWithFlags(&evJoin, cudaEventDisableTiming);
        cudaEventCreateWithFlags(&evG, cudaEventDisableTiming);
        cudaEventCreateWithFlags(&evTail, cudaEventDisableTiming);
        cudaFuncSetAttribute(k_gemm_mma,
                             cudaFuncAttributeMaxDynamicSharedMemorySize,
                             GEMM_SMEM);
    }

    // fork: weight-prep chain on s2, x-conversion on stream 0
    cudaEventRecord(evFork, 0);
    cudaStreamWaitEvent(s2, evFork, 0);
    k_prep1<<<64, 256, 0, s2>>>(w_in, w_x);
    k_prep_w<<<dim3(NTOT / 32, D_MODEL / 32), dim3(32, 8), 0, s2>>>(w_in);
    cudaEventRecord(evJoin, s2);

    k_conv_x<<<(NROWS * D_MODEL) / 512, 256>>>(x, A_log);
    cudaStreamWaitEvent(0, evJoin, 0);

    // main GEMM gets the whole machine
    k_gemm_mma<<<dim3(NTOT / 128, NROWS / 128), 256, GEMM_SMEM>>>();
    cudaEventRecord(evG, 0);
    cudaStreamWaitEvent(s2, evG, 0);

    // batch-pipelined tail: b=1 chain on s2, b=0 chain on stream 0
    k_gemm_dt<<<dim3(D_MODEL / 64, SEQ / 64), 256, 0, s2>>>(w_dt, b_dt, SEQ);
    k_inp_sum<<<SEQ * D_STATE / 256, 256, 0, s2>>>(SEQ);
    k_scanA<<<NC * 4, 256, 0, s2>>>(1);
    k_scanB<<<D_MODEL * D_STATE / 256, 256, 0, s2>>>(1);
    k_scanC<<<NC * 4, 256, 0, s2>>>(Dp, out, 1);
    cudaEventRecord(evTail, s2);

    k_gemm_dt<<<dim3(D_MODEL / 64, SEQ / 64), 256>>>(w_dt, b_dt, 0);
    k_inp_sum<<<SEQ * D_STATE / 256, 256>>>(0);
    k_scanA<<<NC * 4, 256>>>(0);
    k_scanB<<<D_MODEL * D_STATE / 256, 256>>>(0);
    k_scanC<<<NC * 4, 256>>>(Dp, out, 0);

    cudaStreamWaitEvent(0, evTail, 0);
}

// round 17
// speedup vs baseline: 1.1076x; 1.0457x over previous
#include <cuda_runtime.h>
#include <cuda_bf16.h>
#include <cstdint>
#include <math.h>

#define D_MODEL 1024
#define D_STATE 16
#define DT_RANK 64
#define NBATCH 2
#define SEQ 2048
#define NROWS (NBATCH*SEQ)   // 4096
#define NPROJ 96
#define NC 32                // chunks per sequence
#define CT 64                // chunk length (NC*CT == SEQ)
#define NTOT 1152            // 1024 (w_in) + 96 (P) + 32 pad
#define NPART 16             // d-tiles producing inp partials

// ---------------- scratch (device globals) ---------------------------------
__device__ float g_xin [NROWS * D_MODEL];
__device__ float g_proj[NROWS * NPROJ];              // dt_low | B | C
__device__ float g_dt  [NROWS * D_MODEL];
__device__ float g_A   [D_MODEL * D_STATE];          // -exp(A_log)
__device__ float g_A2  [D_MODEL * D_STATE];          // -exp(A_log) * log2(e)
__device__ float g_inp [NROWS * D_STATE];
__device__ float g_inppart[NPART * NROWS * D_STATE]; // per-d-tile partials
__device__ float g_S   [NBATCH * NC * D_MODEL];
__device__ float g_L   [NBATCH * NC * D_MODEL * D_STATE];
__device__ float g_hs  [NBATCH * NC * D_MODEL * D_STATE];
// GEMM operands
__device__ __nv_bfloat16 g_xh [NROWS * D_MODEL];
__device__ __nv_bfloat16 g_xl [NROWS * D_MODEL];
__device__ __nv_bfloat16 g_wth[NTOT * D_MODEL];      // [w_in | P]^T hi  [n][k]
__device__ __nv_bfloat16 g_wtl[NTOT * D_MODEL];      // [w_in | P]^T lo  [n][k]
__device__ float g_P   [D_MODEL * NPROJ];            // w_in @ w_x

#define LOG2E 1.4426950408889634f

// ---------------- PTX helpers (family-portable) -----------------------------
__device__ __forceinline__ uint32_t smem_u32(const void* p) {
    uint32_t a;
    asm("{ .reg .u64 t; cvta.to.shared.u64 t, %1; cvt.u32.u64 %0, t; }"
        : "=r"(a) : "l"(p));
    return a;
}
__device__ __forceinline__ float ex2(float x) {
    float r;
    asm("ex2.approx.ftz.f32 %0, %1;" : "=f"(r) : "f"(x));
    return r;
}
__device__ __forceinline__ void cp16(uint32_t dst, const void* src) {
    asm volatile("cp.async.cg.shared.global [%0], [%1], 16;"
                 :: "r"(dst), "l"(src) : "memory");
}
#define CP_COMMIT() asm volatile("cp.async.commit_group;" ::: "memory")
#define CP_WAIT1()  asm volatile("cp.async.wait_group 1;" ::: "memory")
#define CP_WAIT0()  asm volatile("cp.async.wait_group 0;" ::: "memory")

#define LDSM4(r0,r1,r2,r3,addr) \
    asm volatile("ldmatrix.sync.aligned.m8n8.x4.shared.b16 {%0,%1,%2,%3}, [%4];" \
        : "=r"(r0),"=r"(r1),"=r"(r2),"=r"(r3) : "r"(addr))
#define LDSM2(r0,r1,addr) \
    asm volatile("ldmatrix.sync.aligned.m8n8.x2.shared.b16 {%0,%1}, [%2];" \
        : "=r"(r0),"=r"(r1) : "r"(addr))

#define MMA16816(d, a, b) \
    asm volatile("mma.sync.aligned.m16n8k16.row.col.f32.bf16.bf16.f32 " \
        "{%0,%1,%2,%3}, {%4,%5,%6,%7}, {%8,%9}, {%0,%1,%2,%3};" \
        : "+f"((d)[0]),"+f"((d)[1]),"+f"((d)[2]),"+f"((d)[3]) \
        : "r"((a)[0]),"r"((a)[1]),"r"((a)[2]),"r"((a)[3]), \
          "r"((b)[0]),"r"((b)[1]))

// ---------------- K_conv: split x into bf16 hi/lo (2-wide); A / A2 prep -----
__global__ __launch_bounds__(256) void k_conv_x(const float* __restrict__ x,
                                                const float* __restrict__ A_log) {
    int i = blockIdx.x * 256 + threadIdx.x;
    {
        float2 f = *(const float2*)(x + i * 2);
        __nv_bfloat16 h0 = __float2bfloat16(f.x);
        __nv_bfloat16 h1 = __float2bfloat16(f.y);
        __nv_bfloat162 hv; hv.x = h0; hv.y = h1;
        *(__nv_bfloat162*)(g_xh + i * 2) = hv;
        __nv_bfloat162 lv;
        lv.x = __float2bfloat16(f.x - __bfloat162float(h0));
        lv.y = __float2bfloat16(f.y - __bfloat162float(h1));
        *(__nv_bfloat162*)(g_xl + i * 2) = lv;
    }
    if (i < D_MODEL * D_STATE / 2) {
        float2 al = *(const float2*)(A_log + i * 2);
        float a0 = -__expf(al.x), a1 = -__expf(al.y);
        *(float2*)(g_A  + i * 2) = make_float2(a0, a1);
        *(float2*)(g_A2 + i * 2) = make_float2(a0 * LOG2E, a1 * LOG2E);
    }
}

// ---------------- K_prep1: P = w_in(1024x1024) @ w_x(1024x96) ---------------
__global__ __launch_bounds__(256) void k_prep1(const float* __restrict__ Win,
                                               const float* __restrict__ Wx) {
    __shared__ float As[32][16];
    __shared__ float Bs[32][96];
    int tid = threadIdx.x;
    int row0 = blockIdx.x * 16;
    int tm = tid >> 4, tn = tid & 15;
    float acc[6];
    #pragma unroll
    for (int j = 0; j < 6; j++) acc[j] = 0.f;

    for (int k0 = 0; k0 < D_MODEL; k0 += 32) {
        #pragma unroll
        for (int q = 0; q < 2; q++) {
            int idx = tid + q * 256;
            int m = idx >> 5, kk = idx & 31;
            As[kk][m] = Win[(row0 + m) * D_MODEL + k0 + kk];
        }
        #pragma unroll
        for (int q = 0; q < 3; q++) {
            int f4 = tid + q * 256;
            int kk = f4 / 24, cg = f4 % 24;
            float4 v = *(const float4*)(Wx + (k0 + kk) * NPROJ + cg * 4);
            *(float4*)&Bs[kk][cg * 4] = v;
        }
        __syncthreads();
        #pragma unroll
        for (int k = 0; k < 32; k++) {
            float a = As[k][tm];
            #pragma unroll
            for (int j = 0; j < 6; j++) acc[j] += a * Bs[k][tn * 6 + j];
        }
        __syncthreads();
    }
    #pragma unroll
    for (int j = 0; j < 6; j++)
        g_P[(row0 + tm) * NPROJ + tn * 6 + j] = acc[j];
}

// ---------------- K_prep_w: transpose+split [w_in | P | 0] -> hi/lo ---------
__global__ void k_prep_w(const float* __restrict__ Win) {
    __shared__ float t[32][33];
    int nb = blockIdx.x * 32, kb = blockIdx.y * 32;
    int tx = threadIdx.x, ty = threadIdx.y;
    int tid = ty * 32 + tx;
    #pragma unroll
    for (int i = 0; i < 32; i += 8) {
        int k = kb + ty + i, n = nb + tx;
        float v;
        if (n < 1024)      v = Win[k * D_MODEL + n];
        else if (n < 1120) v = g_P[k * NPROJ + (n - 1024)];
        else               v = 0.f;
        t[ty + i][tx] = v;
    }
    __syncthreads();
    #pragma unroll
    for (int q = 0; q < 2; q++) {
        int idx = tid + q * 256;
        int nn  = idx >> 4;
        int kk2 = (idx & 15) * 2;
        float f0 = t[kk2][nn], f1 = t[kk2 + 1][nn];
        __nv_bfloat16 h0 = __float2bfloat16(f0);
        __nv_bfloat16 h1 = __float2bfloat16(f1);
        __nv_bfloat162 hv; hv.x = h0; hv.y = h1;
        __nv_bfloat162 lv;
        lv.x = __float2bfloat16(f0 - __bfloat162float(h0));
        lv.y = __float2bfloat16(f1 - __bfloat162float(h1));
        int n = nb + nn, k = kb + kk2;
        *(__nv_bfloat162*)(g_wth + n * D_MODEL + k) = hv;
        *(__nv_bfloat162*)(g_wtl + n * D_MODEL + k) = lv;
    }
}

// ---------------- K1: mma GEMM x(4096x1024) @ [w_in|P](1024x1120) -----------
#define TILE_B (128 * 64)
#define STAGE_B (4 * TILE_B)
#define NSTAGE 3
#define GEMM_SMEM (NSTAGE * STAGE_B)
#define NT (D_MODEL / 32)

__device__ __forceinline__ uint32_t swz(int r, int c) {
    return (uint32_t)(r * 64 + ((c ^ ((r >> 1) & 3)) << 4));
}

__global__ __launch_bounds__(256, 2) void k_gemm_mma() {
    extern __shared__ char smem[];
    uint32_t sb = smem_u32(smem);
    int tid = threadIdx.x, wid = tid >> 5, lane = tid & 31;
    int n0 = blockIdx.x * 128, m0 = blockIdx.y * 128;
    int wm = wid >> 2, wn = wid & 3;

    const __nv_bfloat16* srcs[4] = {
        g_xh  + m0 * D_MODEL, g_xl  + m0 * D_MODEL,
        g_wth + n0 * D_MODEL, g_wtl + n0 * D_MODEL };

    int r0 = tid >> 2,        c0 = tid & 3;
    int r1 = (tid >> 2) + 64, c1 = tid & 3;
    uint32_t d0 = swz(r0, c0), d1 = swz(r1, c1);

    #pragma unroll
    for (int s = 0; s < 2; s++) {
        uint32_t stb = sb + s * STAGE_B;
        int k0 = s * 32;
        #pragma unroll
        for (int tk = 0; tk < 4; tk++) {
            cp16(stb + tk * TILE_B + d0, srcs[tk] + r0 * D_MODEL + k0 + c0 * 8);
            cp16(stb + tk * TILE_B + d1, srcs[tk] + r1 * D_MODEL + k0 + c1 * 8);
        }
        CP_COMMIT();
    }

    float acc[4][4][4];
    #pragma unroll
    for (int mf = 0; mf < 4; mf++)
        #pragma unroll
        for (int nf = 0; nf < 4; nf++)
            #pragma unroll
            for (int q = 0; q < 4; q++) acc[mf][nf][q] = 0.f;

    int aRow = wm * 64 + (lane & 15);
    int aCh  = lane >> 4;
    int bRow = wn * 32 + (lane & 7);
    int bCh  = (lane >> 3) & 1;

    int stg_idx = 0;
    for (int kt = 0; kt < NT; kt++) {
        if (kt + 1 < NT) CP_WAIT1(); else CP_WAIT0();
        __syncthreads();

        if (kt + 2 < NT) {
            int k0 = (kt + 2) * 32;
            int s = stg_idx + 2; if (s >= NSTAGE) s -= NSTAGE;
            uint32_t stb = sb + s * STAGE_B;
            #pragma unroll
            for (int tk = 0; tk < 4; tk++) {
                cp16(stb + tk * TILE_B + d0, srcs[tk] + r0 * D_MODEL + k0 + c0 * 8);
                cp16(stb + tk * TILE_B + d1, srcs[tk] + r1 * D_MODEL + k0 + c1 * 8);
            }
            CP_COMMIT();
        }

        uint32_t stg = sb + stg_idx * STAGE_B;
        uint32_t Ah = stg, Al = stg + TILE_B;
        uint32_t Bh = stg + 2 * TILE_B, Bl = stg + 3 * TILE_B;

        #pragma unroll
        for (int ks = 0; ks < 2; ks++) {
            uint32_t bh[4][2], bl[4][2];
            #pragma unroll
            for (int nf = 0; nf < 4; nf++) {
                uint32_t boff = swz(bRow + nf * 8, ks * 2 + bCh);
                LDSM2(bh[nf][0], bh[nf][1], Bh + boff);
                LDSM2(bl[nf][0], bl[nf][1], Bl + boff);
            }
            #pragma unroll
            for (int mf = 0; mf < 4; mf++) {
                uint32_t aoff = swz(aRow + mf * 16, ks * 2 + aCh);
                uint32_t ah[4], al[4];
                LDSM4(ah[0], ah[1], ah[2], ah[3], Ah + aoff);
                LDSM4(al[0], al[1], al[2], al[3], Al + aoff);
                #pragma unroll
                for (int nf = 0; nf < 4; nf++) {
                    MMA16816(acc[mf][nf], ah, bh[nf]);
                    MMA16816(acc[mf][nf], ah, bl[nf]);
                    MMA16816(acc[mf][nf], al, bh[nf]);
                }
            }
        }
        if (++stg_idx == NSTAGE) stg_idx = 0;
    }

    int erow = m0 + wm * 64 + (lane >> 2);
    int ecol = n0 + wn * 32 + (lane & 3) * 2;
    #pragma unroll
    for (int mf = 0; mf < 4; mf++)
        #pragma unroll
        for (int nf = 0; nf < 4; nf++) {
            int col = ecol + nf * 8;
            #pragma unroll
            for (int half = 0; half < 2; half++) {
                int row = erow + mf * 16 + half * 8;
                float v0 = acc[mf][nf][half * 2 + 0];
                float v1 = acc[mf][nf][half * 2 + 1];
                if (col < 1024) {
                    *(float2*)(g_xin + row * D_MODEL + col) = make_float2(v0, v1);
                } else if (col < 1120) {
                    *(float2*)(g_proj + row * NPROJ + (col - 1024)) =
                        make_float2(v0, v1);
                }
            }
        }
}

// ---------------- K3: dt GEMM + fused inp partials (R11-proven) -------------
__global__ __launch_bounds__(256) void k_gemm_dt(
    const float* __restrict__ Wdt, const float* __restrict__ bdt) {
    __shared__ float As[64][68];
    __shared__ float Bs[64][64];
    __shared__ float sA[64][17];
    int tid = threadIdx.x;
    int col0 = blockIdx.x * 64;
    int row0 = blockIdx.y * 64;

    #pragma unroll
    for (int q = 0; q < 16; q++) {
        int idx = tid + q * 256;
        int m = idx >> 6, kk = idx & 63;
        As[kk][m] = g_proj[(row0 + m) * NPROJ + kk];
    }
    #pragma unroll
    for (int q = 0; q < 16; q++) {
        int idx = tid + q * 256;
        int kk = idx >> 6, n = idx & 63;
        Bs[kk][n] = Wdt[kk * D_MODEL + col0 + n];
    }
    #pragma unroll
    for (int q = 0; q < 4; q++) {
        int idx = tid + q * 256;
        int cc = idx >> 4, n = idx & 15;
        sA[cc][n] = g_A[(col0 + cc) * D_STATE + n];
    }
    __syncthreads();

    int tm = tid >> 4, tn = tid & 15;
    float acc[4][4];
    #pragma unroll
    for (int i = 0; i < 4; i++)
        #pragma unroll
        for (int j = 0; j < 4; j++) acc[i][j] = 0.f;

    #pragma unroll 8
    for (int k = 0; k < 64; k++) {
        float4 ra = *(const float4*)&As[k][tm * 4];
        float4 rb = *(const float4*)&Bs[k][tn * 4];
        float a[4] = { ra.x, ra.y, ra.z, ra.w };
        float b[4] = { rb.x, rb.y, rb.z, rb.w };
        #pragma unroll
        for (int i = 0; i < 4; i++)
            #pragma unroll
            for (int j = 0; j < 4; j++) acc[i][j] += a[i] * b[j];
    }

    #pragma unroll
    for (int i = 0; i < 4; i++) {
        int row = row0 + tm * 4 + i;
        float dtv[4];
        #pragma unroll
        for (int j = 0; j < 4; j++) {
            int col = col0 + tn * 4 + j;
            float z = acc[i][j] + bdt[col];
            float sp = fmaxf(z, 0.f) + log1pf(__expf(-fabsf(z)));
            dtv[j] = sp * 0.099f + 0.001f;
        }
        *(float4*)(g_dt + row * D_MODEL + col0 + tn * 4) =
            make_float4(dtv[0], dtv[1], dtv[2], dtv[3]);

        float4 uv = *(const float4*)(g_xin + row * D_MODEL + col0 + tn * 4);
        float p[4] = { dtv[0]*uv.x, dtv[1]*uv.y, dtv[2]*uv.z, dtv[3]*uv.w };
        float part[D_STATE];
        #pragma unroll
        for (int n = 0; n < D_STATE; n++) {
            float s = 0.f;
            #pragma unroll
            for (int j = 0; j < 4; j++) s += p[j] * sA[tn * 4 + j][n];
            part[n] = s;
        }
        #pragma unroll
        for (int n = 0; n < D_STATE; n++) {
            #pragma unroll
            for (int off = 8; off > 0; off >>= 1)
                part[n] += __shfl_down_sync(0xFFFFFFFFu, part[n], off, 16);
        }
        if (tn == 0) {
            #pragma unroll
            for (int n = 0; n < D_STATE; n += 4)
                *(float4*)(g_inppart + (blockIdx.x * NROWS + row) * D_STATE + n) =
                    make_float4(part[n], part[n+1], part[n+2], part[n+3]);
        }
    }
}

// ---------------- K4: inp_sum — fold 16 partials, multiply by B -------------
__global__ __launch_bounds__(256) void k_inp_sum() {
    int idx = blockIdx.x * 256 + threadIdx.x;    // 0..65535
    int r = idx >> 4, n = idx & 15;
    float s = 0.f;
    #pragma unroll
    for (int p = 0; p < NPART; p++)
        s += g_inppart[(p * NROWS + r) * D_STATE + n];
    g_inp[idx] = s * g_proj[r * NPROJ + DT_RANK + n];
}

// ---------------- K5: scan phase A (CT=64) ----------------------------------
__global__ __launch_bounds__(256) void k_scanA() {
    int blk = blockIdx.x;                 // 0..255
    int dgrp = blk & 3;
    int c = (blk >> 2) & (NC - 1);        // 0..31
    int b = blk >> 7;
    int d = dgrp * 256 + threadIdx.x;
    int rbase = b * SEQ + c * CT;

    __shared__ __align__(16) float s_inp[CT * D_STATE];   // 4 KB
    ((float4*)s_inp)[threadIdx.x] =
        ((const float4*)(g_inp + rbase * D_STATE))[threadIdx.x];
    __syncthreads();

    float Ar[D_STATE];
    {
        const float4* Ap = (const float4*)(g_A2 + d * D_STATE);
        #pragma unroll
        for (int q = 0; q < 4; q++) {
            float4 a = Ap[q];
            Ar[q*4+0]=a.x; Ar[q*4+1]=a.y; Ar[q*4+2]=a.z; Ar[q*4+3]=a.w;
        }
    }
    float h[D_STATE];
    #pragma unroll
    for (int n = 0; n < D_STATE; n++) h[n] = 0.f;
    float S = 0.f;

    const float* dtp = g_dt + rbase * D_MODEL + d;
    float dta = dtp[0];
    float dtb = dtp[D_MODEL];

    #pragma unroll 8
    for (int t = 0; t < CT; t++) {
        float cur = dta;
        dta = dtb;
        if (t + 2 < CT) dtb = dtp[(t + 2) * D_MODEL];
        S += cur;
        const float4* ip = (const float4*)(s_inp + t * D_STATE);
        float4 i0 = ip[0], i1 = ip[1], i2 = ip[2], i3 = ip[3];
        float inp[D_STATE] = { i0.x,i0.y,i0.z,i0.w, i1.x,i1.y,i1.z,i1.w,
                               i2.x,i2.y,i2.z,i2.w, i3.x,i3.y,i3.z,i3.w };
        #pragma unroll
        for (int n = 0; n < D_STATE; n++)
            h[n] = ex2(cur * Ar[n]) * h[n] + inp[n];
    }
    int base = (b * NC + c) * D_MODEL + d;
    g_S[base] = S;
    float* Lp = g_L + base * D_STATE;
    #pragma unroll
    for (int q = 0; q < 4; q++)
        ((float4*)Lp)[q] = make_float4(h[q*4+0], h[q*4+1], h[q*4+2], h[q*4+3]);
}

// ---------------- K6: scan phase B (NC=32 steps) ----------------------------
__global__ __launch_bounds__(256) void k_scanB() {
    int idx = blockIdx.x * blockDim.x + threadIdx.x;
    int n = idx & (D_STATE - 1);
    int d = (idx >> 4) & (D_MODEL - 1);
    int b = idx >> 14;
    float a2 = g_A2[d * D_STATE + n];
    float hs = 0.f;
    #pragma unroll 4
    for (int c = 0; c < NC; c++) {
        int base = (b * NC + c) * D_MODEL + d;
        g_hs[base * D_STATE + n] = hs;
        hs = ex2(a2 * g_S[base]) * hs + g_L[base * D_STATE + n];
    }
}

// ---------------- K7: scan phase C (CT=64) ----------------------------------
__global__ __launch_bounds__(256) void k_scanC(
    const float* __restrict__ Dp, float* __restrict__ out) {
    int blk = blockIdx.x;
    int dgrp = blk & 3;
    int c = (blk >> 2) & (NC - 1);
    int b = blk >> 7;
    int d = dgrp * 256 + threadIdx.x;
    int rbase = b * SEQ + c * CT;

    __shared__ __align__(16) float s_inp[CT * D_STATE];   // 4 KB
    __shared__ __align__(16) float s_C[CT * D_STATE];     // 4 KB
    ((float4*)s_inp)[threadIdx.x] =
        ((const float4*)(g_inp + rbase * D_STATE))[threadIdx.x];
    {
        int t = threadIdx.x >> 2, c4 = threadIdx.x & 3;
        ((float4*)s_C)[threadIdx.x] =
            *(const float4*)(g_proj + (rbase + t) * NPROJ + DT_RANK + D_STATE + c4 * 4);
    }
    __syncthreads();

    float Ar[D_STATE], h[D_STATE];
    {
        const float4* Ap = (const float4*)(g_A2 + d * D_STATE);
        #pragma unroll
        for (int q = 0; q < 4; q++) {
            float4 a = Ap[q];
            Ar[q*4+0]=a.x; Ar[q*4+1]=a.y; Ar[q*4+2]=a.z; Ar[q*4+3]=a.w;
        }
        int base = (b * NC + c) * D_MODEL + d;
        const float4* Hp = (const float4*)(g_hs + base * D_STATE);
        #pragma unroll
        for (int q = 0; q < 4; q++) {
            float4 v = Hp[q];
            h[q*4+0]=v.x; h[q*4+1]=v.y; h[q*4+2]=v.z; h[q*4+3]=v.w;
        }
    }
    float dp = Dp[d];

    const float* dtp = g_dt + rbase * D_MODEL + d;
    const float* up  = g_xin + rbase * D_MODEL + d;
    float dta = dtp[0], dtb = dtp[D_MODEL];
    float ua  = up[0],  ub  = up[D_MODEL];

    #pragma unroll 8
    for (int t = 0; t < CT; t++) {
        float ldt = dta, u = ua;
        dta = dtb; ua = ub;
        if (t + 2 < CT) {
            dtb = dtp[(t + 2) * D_MODEL];
            ub  = up[(t + 2) * D_MODEL];
        }
        const float4* ip = (const float4*)(s_inp + t * D_STATE);
        const float4* cp = (const float4*)(s_C + t * D_STATE);
        float4 i0 = ip[0], i1 = ip[1], i2 = ip[2], i3 = ip[3];
        float4 c0 = cp[0], c1 = cp[1], c2 = cp[2], c3 = cp[3];
        float inp[D_STATE] = { i0.x,i0.y,i0.z,i0.w, i1.x,i1.y,i1.z,i1.w,
                               i2.x,i2.y,i2.z,i2.w, i3.x,i3.y,i3.z,i3.w };
        float cm[D_STATE]  = { c0.x,c0.y,c0.z,c0.w, c1.x,c1.y,c1.z,c1.w,
                               c2.x,c2.y,c2.z,c2.w, c3.x,c3.y,c3.z,c3.w };
        float y = dp * u;
        #pragma unroll
        for (int n = 0; n < D_STATE; n++) {
            h[n] = ex2(ldt * Ar[n]) * h[n] + inp[n];
            y += h[n] * cm[n];
        }
        __stcs(out + (rbase + t) * D_MODEL + d, y);
    }
}

// ---------------- launch (R11 schedule) -------------------------------------
extern "C" void kernel_launch(void* const* d_in, const int* in_sizes, int n_in,
                              void* d_out, int out_size) {
    const float* x     = (const float*)d_in[0];
    const float* w_in  = (const float*)d_in[1];
    const float* w_x   = (const float*)d_in[2];
    const float* w_dt  = (const float*)d_in[3];
    const float* b_dt  = (const float*)d_in[4];
    const float* A_log = (const float*)d_in[5];
    const float* Dp    = (const float*)d_in[6];
    float* out = (float*)d_out;

    static cudaStream_t s2 = nullptr;
    static cudaEvent_t evFork = nullptr, evJoin = nullptr;
    if (s2 == nullptr) {
        cudaStreamCreateWithFlags(&s2, cudaStreamNonBlocking);
        cudaEventCreateWithFlags(&evFork, cudaEventDisableTiming);
        cudaEventCreateWithFlags(&evJoin, cudaEventDisableTiming);
        cudaFuncSetAttribute(k_gemm_mma,
                             cudaFuncAttributeMaxDynamicSharedMemorySize,
                             GEMM_SMEM);
    }

    // fork: weight-prep chain on s2, x-conversion on stream 0
    cudaEventRecord(evFork, 0);
    cudaStreamWaitEvent(s2, evFork, 0);
    k_prep1<<<64, 256, 0, s2>>>(w_in, w_x);
    k_prep_w<<<dim3(NTOT / 32, D_MODEL / 32), dim3(32, 8), 0, s2>>>(w_in);
    cudaEventRecord(evJoin, s2);

    k_conv_x<<<(NROWS * D_MODEL) / 512, 256>>>(x, A_log);
    cudaStreamWaitEvent(0, evJoin, 0);

    k_gemm_mma<<<dim3(NTOT / 128, NROWS / 128), 256, GEMM_SMEM>>>();
    k_gemm_dt<<<dim3(D_MODEL / 64, NROWS / 64), 256>>>(w_dt, b_dt);
    k_inp_sum<<<NROWS * D_STATE / 256, 256>>>();
    k_scanA<<<NBATCH * NC * 4, 256>>>();
    k_scanB<<<NBATCH * D_MODEL * D_STATE / 256, 256>>>();
    k_scanC<<<NBATCH * NC * 4, 256>>>(Dp, out);
}